// round 3
// baseline (speedup 1.0000x reference)
#include <cuda_runtime.h>
#include <math.h>

#define S_SCENES 128
#define N_PED    64
#define HID      128
#define TOTAL    (S_SCENES * N_PED)   // 8192
#define QSCALE   0.17677669529663687f // 1/sqrt(32)

// ---------------- device scratch ----------------
__device__ float g_y[TOTAL * 384];    // q | kf | vf  (q pre-scaled)
__device__ float g_ctx[TOTAL * HID];  // attention context
__device__ float g_wk2[HID * 64];     // Wk @ W2
__device__ float g_wv2[HID * 64];     // Wv @ W2
__device__ float g_wco[HID * HID];    // P2 @ out_w
__device__ float g_bias384[384];      // [bq | bk+Wk@b2 | bv+Wv@b2]
__device__ float g_bco[HID];          // proj_b + P2 @ out_b

// ---------------- f32x2 helpers ----------------
__device__ __forceinline__ unsigned long long dup2(float x) {
    unsigned long long r;
    asm("mov.b64 %0, {%1, %1};" : "=l"(r) : "r"(__float_as_uint(x)));
    return r;
}
__device__ __forceinline__ unsigned long long pk2(float lo, float hi) {
    unsigned long long r;
    asm("mov.b64 %0, {%1, %2};" : "=l"(r) : "r"(__float_as_uint(lo)), "r"(__float_as_uint(hi)));
    return r;
}
__device__ __forceinline__ void ffma2(unsigned long long& d,
                                      unsigned long long a, unsigned long long b) {
    asm("fma.rn.f32x2 %0, %1, %2, %0;" : "+l"(d) : "l"(a), "l"(b));
}
__device__ __forceinline__ float2 unpk2(unsigned long long v) {
    unsigned lo, hi;
    asm("mov.b64 {%0, %1}, %2;" : "=r"(lo), "=r"(hi) : "l"(v));
    return make_float2(__uint_as_float(lo), __uint_as_float(hi));
}
union F4U { float4 f4; unsigned long long u[2]; float f[4]; };

// ---------------- K1: combine weights ----------------
__global__ void prep_kernel(const float* __restrict__ ipw,
                            const float* __restrict__ ipb,
                            const float* __restrict__ W2,
                            const float* __restrict__ b2,
                            const float* __restrict__ outw,
                            const float* __restrict__ outb,
                            const float* __restrict__ pw,
                            const float* __restrict__ pb)
{
    int idx = blockIdx.x * blockDim.x + threadIdx.x;
    if (idx < 384) {
        float v = ipb[idx];
        if (idx >= 128) {
            const float* wrow = ipw + idx * 128;
            float acc = 0.f;
            #pragma unroll 8
            for (int d = 0; d < 128; d++) acc += wrow[d] * b2[d];
            v += acc;
        }
        g_bias384[idx] = v;
        return;
    }
    int t = idx - 384;
    if (t < 8192) {
        int hd = t >> 6, c = t & 63;
        const float* wrow = ipw + (128 + hd) * 128;
        float acc = 0.f;
        #pragma unroll 8
        for (int d = 0; d < 128; d++) acc += wrow[d] * W2[d * 64 + c];
        g_wk2[t] = acc;
        return;
    }
    t -= 8192;
    if (t < 8192) {
        int hd = t >> 6, c = t & 63;
        const float* wrow = ipw + (256 + hd) * 128;
        float acc = 0.f;
        #pragma unroll 8
        for (int d = 0; d < 128; d++) acc += wrow[d] * W2[d * 64 + c];
        g_wv2[t] = acc;
        return;
    }
    t -= 8192;
    if (t < 16384) {
        int n = t >> 7, k = t & 127;
        const float* p2 = pw + n * 256 + 128;
        float acc = 0.f;
        #pragma unroll 8
        for (int d = 0; d < 128; d++) acc += p2[d] * outw[d * 128 + k];
        g_wco[t] = acc;
        return;
    }
    t -= 16384;
    if (t < 128) {
        const float* p2 = pw + t * 256 + 128;
        float acc = pb[t];
        #pragma unroll 8
        for (int d = 0; d < 128; d++) acc += p2[d] * outb[d];
        g_bco[t] = acc;
    }
}

// ---------------- GEMM 64x64 tiles, BK=32, 256 threads, 4x4 microtile ----------------
#define TS_P 68

// G1: Y = X @ in_proj_w^T + bias384; q block scaled
__global__ void __launch_bounds__(256) qkv_gemm(const float* __restrict__ X,
                                                const float* __restrict__ W)
{
    __shared__ float As[32][TS_P];   // [k][m]
    __shared__ float Bs[32][TS_P];   // [k][n]
    int m0 = blockIdx.x * 64, n0 = blockIdx.y * 64;
    int tid = threadIdx.x, tx = tid & 15, ty = tid >> 4;

    unsigned long long acc[2][4];
    #pragma unroll
    for (int p = 0; p < 2; p++)
        #pragma unroll
        for (int c = 0; c < 4; c++) acc[p][c] = 0ULL;

    int rowL[2], kqL[2];
    #pragma unroll
    for (int i = 0; i < 2; i++) { int idx = tid + i * 256; rowL[i] = idx >> 3; kqL[i] = idx & 7; }

    float4 pa[2], pb[2];
    #pragma unroll
    for (int i = 0; i < 2; i++) {
        pa[i] = *(const float4*)&X[(m0 + rowL[i]) * 128 + kqL[i] * 4];
        pb[i] = *(const float4*)&W[(n0 + rowL[i]) * 128 + kqL[i] * 4];
    }

    for (int kc = 0; kc < 4; kc++) {
        #pragma unroll
        for (int i = 0; i < 2; i++) {
            As[kqL[i] * 4 + 0][rowL[i]] = pa[i].x;
            As[kqL[i] * 4 + 1][rowL[i]] = pa[i].y;
            As[kqL[i] * 4 + 2][rowL[i]] = pa[i].z;
            As[kqL[i] * 4 + 3][rowL[i]] = pa[i].w;
            Bs[kqL[i] * 4 + 0][rowL[i]] = pb[i].x;
            Bs[kqL[i] * 4 + 1][rowL[i]] = pb[i].y;
            Bs[kqL[i] * 4 + 2][rowL[i]] = pb[i].z;
            Bs[kqL[i] * 4 + 3][rowL[i]] = pb[i].w;
        }
        __syncthreads();
        if (kc < 3) {
            int k0 = (kc + 1) * 32;
            #pragma unroll
            for (int i = 0; i < 2; i++) {
                pa[i] = *(const float4*)&X[(m0 + rowL[i]) * 128 + k0 + kqL[i] * 4];
                pb[i] = *(const float4*)&W[(n0 + rowL[i]) * 128 + k0 + kqL[i] * 4];
            }
        }
        #pragma unroll
        for (int k = 0; k < 32; k++) {
            F4U a, b;
            a.f4 = *(const float4*)&As[k][ty * 4];
            b.f4 = *(const float4*)&Bs[k][tx * 4];
            unsigned long long bd[4];
            #pragma unroll
            for (int c = 0; c < 4; c++) bd[c] = dup2(b.f[c]);
            #pragma unroll
            for (int c = 0; c < 4; c++) {
                ffma2(acc[0][c], a.u[0], bd[c]);
                ffma2(acc[1][c], a.u[1], bd[c]);
            }
        }
        __syncthreads();
    }
    float scale = (n0 < 128) ? QSCALE : 1.0f;
    int n = n0 + tx * 4;
    float4 b4 = *(const float4*)&g_bias384[n];
    #pragma unroll
    for (int p = 0; p < 2; p++) {
        float2 p0 = unpk2(acc[p][0]), p1 = unpk2(acc[p][1]);
        float2 p2 = unpk2(acc[p][2]), p3 = unpk2(acc[p][3]);
        int m = m0 + ty * 4 + p * 2;
        float4 lo = make_float4((p0.x + b4.x) * scale, (p1.x + b4.y) * scale,
                                (p2.x + b4.z) * scale, (p3.x + b4.w) * scale);
        float4 hi = make_float4((p0.y + b4.x) * scale, (p1.y + b4.y) * scale,
                                (p2.y + b4.z) * scale, (p3.y + b4.w) * scale);
        *(float4*)&g_y[m * 384 + n] = lo;
        *(float4*)&g_y[(m + 1) * 384 + n] = hi;
    }
}

// G2: OUT = X @ P1^T + CTX @ Wco^T + bco
__global__ void __launch_bounds__(256) out_gemm(const float* __restrict__ X,
                                                const float* __restrict__ PW,
                                                float* __restrict__ OUT)
{
    __shared__ float As[32][TS_P];
    __shared__ float Bs[32][TS_P];
    int m0 = blockIdx.x * 64, n0 = blockIdx.y * 64;
    int tid = threadIdx.x, tx = tid & 15, ty = tid >> 4;

    unsigned long long acc[2][4];
    #pragma unroll
    for (int p = 0; p < 2; p++)
        #pragma unroll
        for (int c = 0; c < 4; c++) acc[p][c] = 0ULL;

    int rowL[2], kqL[2];
    #pragma unroll
    for (int i = 0; i < 2; i++) { int idx = tid + i * 256; rowL[i] = idx >> 3; kqL[i] = idx & 7; }

    float4 pa[2], pb[2];
    #pragma unroll
    for (int i = 0; i < 2; i++) {
        pa[i] = *(const float4*)&X[(m0 + rowL[i]) * 128 + kqL[i] * 4];
        pb[i] = *(const float4*)&PW[(n0 + rowL[i]) * 256 + kqL[i] * 4];
    }

    for (int kc = 0; kc < 8; kc++) {
        #pragma unroll
        for (int i = 0; i < 2; i++) {
            As[kqL[i] * 4 + 0][rowL[i]] = pa[i].x;
            As[kqL[i] * 4 + 1][rowL[i]] = pa[i].y;
            As[kqL[i] * 4 + 2][rowL[i]] = pa[i].z;
            As[kqL[i] * 4 + 3][rowL[i]] = pa[i].w;
            Bs[kqL[i] * 4 + 0][rowL[i]] = pb[i].x;
            Bs[kqL[i] * 4 + 1][rowL[i]] = pb[i].y;
            Bs[kqL[i] * 4 + 2][rowL[i]] = pb[i].z;
            Bs[kqL[i] * 4 + 3][rowL[i]] = pb[i].w;
        }
        __syncthreads();
        if (kc < 7) {
            int knext = kc + 1;
            int kcol = (knext & 3) * 32;
            if (knext < 4) {
                #pragma unroll
                for (int i = 0; i < 2; i++) {
                    pa[i] = *(const float4*)&X[(m0 + rowL[i]) * 128 + kcol + kqL[i] * 4];
                    pb[i] = *(const float4*)&PW[(n0 + rowL[i]) * 256 + kcol + kqL[i] * 4];
                }
            } else {
                #pragma unroll
                for (int i = 0; i < 2; i++) {
                    pa[i] = *(const float4*)&g_ctx[(m0 + rowL[i]) * 128 + kcol + kqL[i] * 4];
                    pb[i] = *(const float4*)&g_wco[(n0 + rowL[i]) * 128 + kcol + kqL[i] * 4];
                }
            }
        }
        #pragma unroll
        for (int k = 0; k < 32; k++) {
            F4U a, b;
            a.f4 = *(const float4*)&As[k][ty * 4];
            b.f4 = *(const float4*)&Bs[k][tx * 4];
            unsigned long long bd[4];
            #pragma unroll
            for (int c = 0; c < 4; c++) bd[c] = dup2(b.f[c]);
            #pragma unroll
            for (int c = 0; c < 4; c++) {
                ffma2(acc[0][c], a.u[0], bd[c]);
                ffma2(acc[1][c], a.u[1], bd[c]);
            }
        }
        __syncthreads();
    }
    int n = n0 + tx * 4;
    float4 b4 = *(const float4*)&g_bco[n];
    #pragma unroll
    for (int p = 0; p < 2; p++) {
        float2 p0 = unpk2(acc[p][0]), p1 = unpk2(acc[p][1]);
        float2 p2 = unpk2(acc[p][2]), p3 = unpk2(acc[p][3]);
        int m = m0 + ty * 4 + p * 2;
        float4 lo = make_float4(p0.x + b4.x, p1.x + b4.y, p2.x + b4.z, p3.x + b4.w);
        float4 hi = make_float4(p0.y + b4.x, p1.y + b4.y, p2.y + b4.z, p3.y + b4.w);
        *(float4*)&OUT[m * 128 + n] = lo;
        *(float4*)&OUT[(m + 1) * 128 + n] = hi;
    }
}

// ---------------- K3: per-scene attention core ----------------
#define OFF_KF   8192
#define OFF_WK2  16640
#define OFF_VF   25088
#define OFF_WV2  33792
#define OFF_W1B  42496
#define OFF_P2   42752
#define OFF_TW   42880
#define OFF_SC   46976
#define OFF_GW   51072
#define ATTN_SMEM_FLOATS 55168

__global__ void __launch_bounds__(512) attn_kernel(const float* __restrict__ pos,
                                                   const float* __restrict__ W1,
                                                   const float* __restrict__ b1)
{
    extern __shared__ float sm[];
    float*  Q   = sm;
    float*  KFt = sm + OFF_KF;    // [d][j]  stride 66
    float*  WK2 = sm + OFF_WK2;   // [d][c]  stride 66
    float*  VFt = sm + OFF_VF;    // [vd][j] stride 68
    float*  WV2 = sm + OFF_WV2;   // [vd][c] stride 68
    float4* W1B = (float4*)(sm + OFF_W1B);
    float2* P2  = (float2*)(sm + OFF_P2);
    float*  Tw  = sm + OFF_TW;    // per-warp [c][h]
    float*  SC  = sm + OFF_SC;    // per-warp [h][j]
    float*  Gw  = sm + OFF_GW;    // per-warp [h][c]

    int s = blockIdx.x, tid = threadIdx.x;
    int w = tid >> 5, lane = tid & 31;
    int base = s * 64;

    #pragma unroll
    for (int it = 0; it < 4; it++) {
        int idx = tid + it * 512;
        int r = idx >> 5, cq = idx & 31;
        *(float4*)&Q[r * 128 + cq * 4] = *(const float4*)&g_y[(base + r) * 384 + cq * 4];
    }
    #pragma unroll
    for (int it = 0; it < 16; it++) {
        int idx = tid + it * 512;
        int r = idx >> 7, c = idx & 127;
        KFt[c * 66 + r] = g_y[(base + r) * 384 + 128 + c];
        VFt[c * 68 + r] = g_y[(base + r) * 384 + 256 + c];
    }
    #pragma unroll
    for (int it = 0; it < 16; it++) {
        int idx = tid + it * 512;
        int row = idx >> 6, c = idx & 63;
        WK2[row * 66 + c] = g_wk2[idx];
    }
    #pragma unroll
    for (int it = 0; it < 4; it++) {
        int idx = tid + it * 512;
        int row = idx >> 4, cq = idx & 15;
        *(float4*)&WV2[row * 68 + cq * 4] = *(const float4*)&g_wv2[row * 64 + cq * 4];
    }
    if (tid < 64) {
        W1B[tid] = make_float4(W1[tid * 2], W1[tid * 2 + 1], b1[tid], 0.f);
        P2[tid]  = *(const float2*)&pos[(base + tid) * 2];
    }
    __syncthreads();

    float* myT  = Tw + w * 256;
    float* mySC = SC + w * 256;
    float* myG  = Gw + w * 256;
    int c0 = 2 * lane, c1 = c0 + 1;     // also j0, j1

    float4 wp0 = W1B[c0], wp1 = W1B[c1];
    float2 pj0 = P2[c0],  pj1 = P2[c1];

    for (int i = w; i < 64; i += 16) {
        const float* qrow = Q + i * 128;
        float2 pi = P2[i];
        float dxj0 = pj0.x - pi.x, dyj0 = pj0.y - pi.y;
        float dxj1 = pj1.x - pi.x, dyj1 = pj1.y - pi.y;

        // ---- merged: t[h][c-pair] and qk-score[h][j-pair] over d ----
        unsigned long long tacc[4], sacc[4];
        #pragma unroll
        for (int h = 0; h < 4; h++) { tacc[h] = 0ULL; sacc[h] = 0ULL; }
        #pragma unroll
        for (int h = 0; h < 4; h++) {
            #pragma unroll
            for (int dq = 0; dq < 8; dq++) {
                int dbase = h * 32 + dq * 4;
                F4U q4; q4.f4 = *(const float4*)&qrow[dbase];
                #pragma unroll
                for (int u = 0; u < 4; u++) {
                    int d = dbase + u;
                    unsigned long long kk = *(const unsigned long long*)&KFt[d * 66 + c0];
                    unsigned long long wk = *(const unsigned long long*)&WK2[d * 66 + c0];
                    unsigned long long qd = dup2(q4.f[u]);
                    ffma2(tacc[h], qd, wk);
                    ffma2(sacc[h], qd, kk);
                }
            }
        }
        // write t (layout [c][h] -> natural head-pairs), repack scores into head-pairs
        unsigned long long aj0_01, aj0_23, aj1_01, aj1_23;
        {
            float2 t0 = unpk2(tacc[0]), t1 = unpk2(tacc[1]);
            float2 t2 = unpk2(tacc[2]), t3 = unpk2(tacc[3]);
            *(float4*)&myT[c0 * 4] = make_float4(t0.x, t1.x, t2.x, t3.x);
            *(float4*)&myT[c1 * 4] = make_float4(t0.y, t1.y, t2.y, t3.y);
            float2 s0 = unpk2(sacc[0]), s1 = unpk2(sacc[1]);
            float2 s2 = unpk2(sacc[2]), s3 = unpk2(sacc[3]);
            aj0_01 = pk2(s0.x, s1.x); aj0_23 = pk2(s2.x, s3.x);
            aj1_01 = pk2(s0.y, s1.y); aj1_23 = pk2(s2.y, s3.y);
        }
        __syncwarp();

        // ---- rel-encoding contribution to scores (head-pair FFMA2) ----
        #pragma unroll 8
        for (int c = 0; c < 64; c++) {
            float4 wb = W1B[c];
            F4U tv; tv.f4 = *(const float4*)&myT[c * 4];
            float h0 = fmaxf(fmaf(wb.x, dxj0, fmaf(wb.y, dyj0, wb.z)), 0.f);
            float h1 = fmaxf(fmaf(wb.x, dxj1, fmaf(wb.y, dyj1, wb.z)), 0.f);
            unsigned long long h0d = dup2(h0), h1d = dup2(h1);
            ffma2(aj0_01, tv.u[0], h0d);
            ffma2(aj0_23, tv.u[1], h0d);
            ffma2(aj1_01, tv.u[0], h1d);
            ffma2(aj1_23, tv.u[1], h1d);
        }

        // ---- softmax per head ----
        float a0[4], a1[4];
        {
            float2 u01j0 = unpk2(aj0_01), u23j0 = unpk2(aj0_23);
            float2 u01j1 = unpk2(aj1_01), u23j1 = unpk2(aj1_23);
            a0[0] = u01j0.x; a0[1] = u01j0.y; a0[2] = u23j0.x; a0[3] = u23j0.y;
            a1[0] = u01j1.x; a1[1] = u01j1.y; a1[2] = u23j1.x; a1[3] = u23j1.y;
        }
        #pragma unroll
        for (int h = 0; h < 4; h++) {
            float m = fmaxf(a0[h], a1[h]);
            #pragma unroll
            for (int off = 16; off; off >>= 1)
                m = fmaxf(m, __shfl_xor_sync(0xffffffffu, m, off));
            float e0 = __expf(a0[h] - m), e1 = __expf(a1[h] - m);
            float ss = e0 + e1;
            #pragma unroll
            for (int off = 16; off; off >>= 1)
                ss += __shfl_xor_sync(0xffffffffu, ss, off);
            float rinv = 1.f / ss;
            *(float2*)&mySC[h * 64 + c0] = make_float2(e0 * rinv, e1 * rinv);
        }
        __syncwarp();

        // ---- g[h][c-pair] = sum_j attn[h][j] * hid[j][c] ----
        {
            float g0[4] = {0, 0, 0, 0}, g1[4] = {0, 0, 0, 0};
            #pragma unroll 4
            for (int j = 0; j < 64; j++) {
                float2 pj = P2[j];
                float dx = pj.x - pi.x, dy = pj.y - pi.y;
                float h0 = fmaxf(fmaf(wp0.x, dx, fmaf(wp0.y, dy, wp0.z)), 0.f);
                float h1 = fmaxf(fmaf(wp1.x, dx, fmaf(wp1.y, dy, wp1.z)), 0.f);
                #pragma unroll
                for (int h = 0; h < 4; h++) {
                    float a = mySC[h * 64 + j];
                    g0[h] = fmaf(a, h0, g0[h]);
                    g1[h] = fmaf(a, h1, g1[h]);
                }
            }
            #pragma unroll
            for (int h = 0; h < 4; h++)
                *(float2*)&myG[h * 64 + c0] = make_float2(g0[h], g1[h]);
        }
        __syncwarp();

        // ---- ctx[i][h*32+lane] = attn@vf + g@Wv2^T (packed FFMA2) ----
        #pragma unroll
        for (int h = 0; h < 4; h++) {
            unsigned long long pacc = 0ULL;
            const float* vr = VFt + (h * 32 + lane) * 68;
            const float* ar = mySC + h * 64;
            #pragma unroll
            for (int jq = 0; jq < 16; jq++) {
                F4U av, vv;
                av.f4 = *(const float4*)&ar[jq * 4];
                vv.f4 = *(const float4*)&vr[jq * 4];
                ffma2(pacc, av.u[0], vv.u[0]);
                ffma2(pacc, av.u[1], vv.u[1]);
            }
            const float* wr = WV2 + (h * 32 + lane) * 68;
            const float* gr = myG + h * 64;
            #pragma unroll
            for (int cq = 0; cq < 16; cq++) {
                F4U gv, wv;
                gv.f4 = *(const float4*)&gr[cq * 4];
                wv.f4 = *(const float4*)&wr[cq * 4];
                ffma2(pacc, gv.u[0], wv.u[0]);
                ffma2(pacc, gv.u[1], wv.u[1]);
            }
            float2 pr = unpk2(pacc);
            g_ctx[(base + i) * 128 + h * 32 + lane] = pr.x + pr.y;
        }
        __syncwarp();
    }
}

// ---------------- launch ----------------
extern "C" void kernel_launch(void* const* d_in, const int* in_sizes, int n_in,
                              void* d_out, int out_size)
{
    const float* node_features = (const float*)d_in[0];
    const float* positions     = (const float*)d_in[1];
    const float* W1            = (const float*)d_in[2];
    const float* b1            = (const float*)d_in[3];
    const float* W2            = (const float*)d_in[4];
    const float* b2            = (const float*)d_in[5];
    const float* in_proj_w     = (const float*)d_in[6];
    const float* in_proj_b     = (const float*)d_in[7];
    const float* out_w         = (const float*)d_in[8];
    const float* out_b         = (const float*)d_in[9];
    const float* proj_w        = (const float*)d_in[10];
    const float* proj_b        = (const float*)d_in[11];
    float* out = (float*)d_out;

    size_t attn_smem = (size_t)ATTN_SMEM_FLOATS * sizeof(float);
    cudaFuncSetAttribute(attn_kernel, cudaFuncAttributeMaxDynamicSharedMemorySize,
                         (int)attn_smem);

    prep_kernel<<<130, 256>>>(in_proj_w, in_proj_b, W2, b2, out_w, out_b, proj_w, proj_b);
    qkv_gemm<<<dim3(TOTAL / 64, 384 / 64), 256>>>(node_features, in_proj_w);
    attn_kernel<<<S_SCENES, 512, attn_smem>>>(positions, W1, b1);
    out_gemm<<<dim3(TOTAL / 64, 128 / 64), 256>>>(node_features, proj_w, out);
}

// round 4
// speedup vs baseline: 1.0833x; 1.0833x over previous
#include <cuda_runtime.h>
#include <math.h>

#define S_SCENES 128
#define N_PED    64
#define HID      128
#define TOTAL    (S_SCENES * N_PED)   // 8192
#define QSCALE   0.17677669529663687f // 1/sqrt(32)

// ---------------- device scratch ----------------
__device__ float g_y[TOTAL * 384];    // q | kf | vf  (q pre-scaled)
__device__ float g_ctx[TOTAL * HID];  // attention context
__device__ float g_wk2[HID * 64];     // Wk @ W2
__device__ float g_wv2[HID * 64];     // Wv @ W2
__device__ float g_wco[HID * HID];    // P2 @ out_w
__device__ float g_bias384[384];      // [bq | bk+Wk@b2 | bv+Wv@b2]
__device__ float g_bco[HID];          // proj_b + P2 @ out_b

// ---------------- f32x2 helpers ----------------
__device__ __forceinline__ unsigned long long dup2(float x) {
    unsigned long long r;
    asm("mov.b64 %0, {%1, %1};" : "=l"(r) : "r"(__float_as_uint(x)));
    return r;
}
__device__ __forceinline__ unsigned long long pk2(float lo, float hi) {
    unsigned long long r;
    asm("mov.b64 %0, {%1, %2};" : "=l"(r) : "r"(__float_as_uint(lo)), "r"(__float_as_uint(hi)));
    return r;
}
__device__ __forceinline__ void ffma2(unsigned long long& d,
                                      unsigned long long a, unsigned long long b) {
    asm("fma.rn.f32x2 %0, %1, %2, %0;" : "+l"(d) : "l"(a), "l"(b));
}
__device__ __forceinline__ float2 unpk2(unsigned long long v) {
    unsigned lo, hi;
    asm("mov.b64 {%0, %1}, %2;" : "=r"(lo), "=r"(hi) : "l"(v));
    return make_float2(__uint_as_float(lo), __uint_as_float(hi));
}
union F4U { float4 f4; unsigned long long u[2]; float f[4]; };

// ---------------- K1: combine weights ----------------
__global__ void prep_kernel(const float* __restrict__ ipw,
                            const float* __restrict__ ipb,
                            const float* __restrict__ W2,
                            const float* __restrict__ b2,
                            const float* __restrict__ outw,
                            const float* __restrict__ outb,
                            const float* __restrict__ pw,
                            const float* __restrict__ pb)
{
    int idx = blockIdx.x * blockDim.x + threadIdx.x;
    if (idx < 384) {
        float v = ipb[idx];
        if (idx >= 128) {
            const float* wrow = ipw + idx * 128;
            float acc = 0.f;
            #pragma unroll 8
            for (int d = 0; d < 128; d++) acc += wrow[d] * b2[d];
            v += acc;
        }
        g_bias384[idx] = v;
        return;
    }
    int t = idx - 384;
    if (t < 8192) {
        int hd = t >> 6, c = t & 63;
        const float* wrow = ipw + (128 + hd) * 128;
        float acc = 0.f;
        #pragma unroll 8
        for (int d = 0; d < 128; d++) acc += wrow[d] * W2[d * 64 + c];
        g_wk2[t] = acc;
        return;
    }
    t -= 8192;
    if (t < 8192) {
        int hd = t >> 6, c = t & 63;
        const float* wrow = ipw + (256 + hd) * 128;
        float acc = 0.f;
        #pragma unroll 8
        for (int d = 0; d < 128; d++) acc += wrow[d] * W2[d * 64 + c];
        g_wv2[t] = acc;
        return;
    }
    t -= 8192;
    if (t < 16384) {
        int n = t >> 7, k = t & 127;
        const float* p2 = pw + n * 256 + 128;
        float acc = 0.f;
        #pragma unroll 8
        for (int d = 0; d < 128; d++) acc += p2[d] * outw[d * 128 + k];
        g_wco[t] = acc;
        return;
    }
    t -= 16384;
    if (t < 128) {
        const float* p2 = pw + t * 256 + 128;
        float acc = pb[t];
        #pragma unroll 8
        for (int d = 0; d < 128; d++) acc += p2[d] * outb[d];
        g_bco[t] = acc;
    }
}

// ---------------- GEMMs: R2 config (128x64 tile, BK=32, 256 thr, 8x4 microtile) ----------------
#define AS_P 132
#define BS_P 68

__global__ void __launch_bounds__(256) qkv_gemm(const float* __restrict__ X,
                                                const float* __restrict__ W)
{
    __shared__ float As[32][AS_P];   // [k][m]
    __shared__ float Bs[32][BS_P];   // [k][n]
    int m0 = blockIdx.x * 128, n0 = blockIdx.y * 64;
    int tid = threadIdx.x, tx = tid & 15, ty = tid >> 4;

    unsigned long long acc[4][4];
    #pragma unroll
    for (int r = 0; r < 4; r++)
        #pragma unroll
        for (int c = 0; c < 4; c++) acc[r][c] = 0ULL;

    float4 pa[4], pb[2];
    int rowA[4], kqA[4], rowB[2], kqB[2];
    #pragma unroll
    for (int i = 0; i < 4; i++) { int idx = tid + i * 256; rowA[i] = idx >> 3; kqA[i] = idx & 7; }
    #pragma unroll
    for (int i = 0; i < 2; i++) { int idx = tid + i * 256; rowB[i] = idx >> 3; kqB[i] = idx & 7; }

    #pragma unroll
    for (int i = 0; i < 4; i++) pa[i] = *(const float4*)&X[(m0 + rowA[i]) * 128 + kqA[i] * 4];
    #pragma unroll
    for (int i = 0; i < 2; i++) pb[i] = *(const float4*)&W[(n0 + rowB[i]) * 128 + kqB[i] * 4];

    for (int kc = 0; kc < 4; kc++) {
        #pragma unroll
        for (int i = 0; i < 4; i++) {
            As[kqA[i] * 4 + 0][rowA[i]] = pa[i].x;
            As[kqA[i] * 4 + 1][rowA[i]] = pa[i].y;
            As[kqA[i] * 4 + 2][rowA[i]] = pa[i].z;
            As[kqA[i] * 4 + 3][rowA[i]] = pa[i].w;
        }
        #pragma unroll
        for (int i = 0; i < 2; i++) {
            Bs[kqB[i] * 4 + 0][rowB[i]] = pb[i].x;
            Bs[kqB[i] * 4 + 1][rowB[i]] = pb[i].y;
            Bs[kqB[i] * 4 + 2][rowB[i]] = pb[i].z;
            Bs[kqB[i] * 4 + 3][rowB[i]] = pb[i].w;
        }
        __syncthreads();
        if (kc < 3) {
            int k0 = (kc + 1) * 32;
            #pragma unroll
            for (int i = 0; i < 4; i++) pa[i] = *(const float4*)&X[(m0 + rowA[i]) * 128 + k0 + kqA[i] * 4];
            #pragma unroll
            for (int i = 0; i < 2; i++) pb[i] = *(const float4*)&W[(n0 + rowB[i]) * 128 + k0 + kqB[i] * 4];
        }
        #pragma unroll
        for (int k = 0; k < 32; k++) {
            F4U a0, a1, b;
            a0.f4 = *(const float4*)&As[k][ty * 8];
            a1.f4 = *(const float4*)&As[k][ty * 8 + 4];
            b.f4  = *(const float4*)&Bs[k][tx * 4];
            unsigned long long bd[4];
            #pragma unroll
            for (int c = 0; c < 4; c++) bd[c] = dup2(b.f[c]);
            #pragma unroll
            for (int c = 0; c < 4; c++) {
                ffma2(acc[0][c], a0.u[0], bd[c]);
                ffma2(acc[1][c], a0.u[1], bd[c]);
                ffma2(acc[2][c], a1.u[0], bd[c]);
                ffma2(acc[3][c], a1.u[1], bd[c]);
            }
        }
        __syncthreads();
    }
    float scale = (n0 < 128) ? QSCALE : 1.0f;
    int n = n0 + tx * 4;
    float4 b4 = *(const float4*)&g_bias384[n];
    #pragma unroll
    for (int r2 = 0; r2 < 4; r2++) {
        float2 p0 = unpk2(acc[r2][0]), p1 = unpk2(acc[r2][1]);
        float2 p2 = unpk2(acc[r2][2]), p3 = unpk2(acc[r2][3]);
        int m = m0 + ty * 8 + r2 * 2;
        float4 lo = make_float4((p0.x + b4.x) * scale, (p1.x + b4.y) * scale,
                                (p2.x + b4.z) * scale, (p3.x + b4.w) * scale);
        float4 hi = make_float4((p0.y + b4.x) * scale, (p1.y + b4.y) * scale,
                                (p2.y + b4.z) * scale, (p3.y + b4.w) * scale);
        *(float4*)&g_y[m * 384 + n] = lo;
        *(float4*)&g_y[(m + 1) * 384 + n] = hi;
    }
}

__global__ void __launch_bounds__(256) out_gemm(const float* __restrict__ X,
                                                const float* __restrict__ PW,
                                                float* __restrict__ OUT)
{
    __shared__ float As[32][AS_P];
    __shared__ float Bs[32][BS_P];
    int m0 = blockIdx.x * 128, n0 = blockIdx.y * 64;
    int tid = threadIdx.x, tx = tid & 15, ty = tid >> 4;

    unsigned long long acc[4][4];
    #pragma unroll
    for (int r = 0; r < 4; r++)
        #pragma unroll
        for (int c = 0; c < 4; c++) acc[r][c] = 0ULL;

    float4 pa[4], pb[2];
    int rowA[4], kqA[4], rowB[2], kqB[2];
    #pragma unroll
    for (int i = 0; i < 4; i++) { int idx = tid + i * 256; rowA[i] = idx >> 3; kqA[i] = idx & 7; }
    #pragma unroll
    for (int i = 0; i < 2; i++) { int idx = tid + i * 256; rowB[i] = idx >> 3; kqB[i] = idx & 7; }

    #pragma unroll
    for (int i = 0; i < 4; i++) pa[i] = *(const float4*)&X[(m0 + rowA[i]) * 128 + kqA[i] * 4];
    #pragma unroll
    for (int i = 0; i < 2; i++) pb[i] = *(const float4*)&PW[(n0 + rowB[i]) * 256 + kqB[i] * 4];

    for (int kc = 0; kc < 8; kc++) {
        #pragma unroll
        for (int i = 0; i < 4; i++) {
            As[kqA[i] * 4 + 0][rowA[i]] = pa[i].x;
            As[kqA[i] * 4 + 1][rowA[i]] = pa[i].y;
            As[kqA[i] * 4 + 2][rowA[i]] = pa[i].z;
            As[kqA[i] * 4 + 3][rowA[i]] = pa[i].w;
        }
        #pragma unroll
        for (int i = 0; i < 2; i++) {
            Bs[kqB[i] * 4 + 0][rowB[i]] = pb[i].x;
            Bs[kqB[i] * 4 + 1][rowB[i]] = pb[i].y;
            Bs[kqB[i] * 4 + 2][rowB[i]] = pb[i].z;
            Bs[kqB[i] * 4 + 3][rowB[i]] = pb[i].w;
        }
        __syncthreads();
        if (kc < 7) {
            int knext = kc + 1;
            int kcol = (knext & 3) * 32;
            if (knext < 4) {
                #pragma unroll
                for (int i = 0; i < 4; i++) pa[i] = *(const float4*)&X[(m0 + rowA[i]) * 128 + kcol + kqA[i] * 4];
                #pragma unroll
                for (int i = 0; i < 2; i++) pb[i] = *(const float4*)&PW[(n0 + rowB[i]) * 256 + kcol + kqB[i] * 4];
            } else {
                #pragma unroll
                for (int i = 0; i < 4; i++) pa[i] = *(const float4*)&g_ctx[(m0 + rowA[i]) * 128 + kcol + kqA[i] * 4];
                #pragma unroll
                for (int i = 0; i < 2; i++) pb[i] = *(const float4*)&g_wco[(n0 + rowB[i]) * 128 + kcol + kqB[i] * 4];
            }
        }
        #pragma unroll
        for (int k = 0; k < 32; k++) {
            F4U a0, a1, b;
            a0.f4 = *(const float4*)&As[k][ty * 8];
            a1.f4 = *(const float4*)&As[k][ty * 8 + 4];
            b.f4  = *(const float4*)&Bs[k][tx * 4];
            unsigned long long bd[4];
            #pragma unroll
            for (int c = 0; c < 4; c++) bd[c] = dup2(b.f[c]);
            #pragma unroll
            for (int c = 0; c < 4; c++) {
                ffma2(acc[0][c], a0.u[0], bd[c]);
                ffma2(acc[1][c], a0.u[1], bd[c]);
                ffma2(acc[2][c], a1.u[0], bd[c]);
                ffma2(acc[3][c], a1.u[1], bd[c]);
            }
        }
        __syncthreads();
    }
    int n = n0 + tx * 4;
    float4 b4 = *(const float4*)&g_bco[n];
    #pragma unroll
    for (int r2 = 0; r2 < 4; r2++) {
        float2 p0 = unpk2(acc[r2][0]), p1 = unpk2(acc[r2][1]);
        float2 p2 = unpk2(acc[r2][2]), p3 = unpk2(acc[r2][3]);
        int m = m0 + ty * 8 + r2 * 2;
        float4 lo = make_float4(p0.x + b4.x, p1.x + b4.y, p2.x + b4.z, p3.x + b4.w);
        float4 hi = make_float4(p0.y + b4.x, p1.y + b4.y, p2.y + b4.z, p3.y + b4.w);
        *(float4*)&OUT[m * 128 + n] = lo;
        *(float4*)&OUT[(m + 1) * 128 + n] = hi;
    }
}

// ---------------- K3: attention, 1024 threads, 32 warps x 2 queries ----------------
// smem floats: KFt[128*66]=8448 | WK2[128*66]=8448 | VFt[128*68]=8704 | WV2[128*68]=8704 |
//              W1B[64*4]=256 | P2[64*2]=128 | per-warp TG+SC: 32*512=16384  => 51072 (199.5KB)
#define OFF_WK2  8448
#define OFF_VF   16896
#define OFF_WV2  25600
#define OFF_W1B  34304
#define OFF_P2   34560
#define OFF_BUF  34688
#define ATTN_SMEM_FLOATS (34688 + 32 * 512)

__global__ void __launch_bounds__(1024) attn_kernel(const float* __restrict__ pos,
                                                    const float* __restrict__ W1,
                                                    const float* __restrict__ b1)
{
    extern __shared__ float sm[];
    float*  KFt = sm;             // [d][j]  stride 66
    float*  WK2 = sm + OFF_WK2;   // [d][c]  stride 66
    float*  VFt = sm + OFF_VF;    // [vd][j] stride 68
    float*  WV2 = sm + OFF_WV2;   // [vd][c] stride 68
    float4* W1B = (float4*)(sm + OFF_W1B);
    float2* P2  = (float2*)(sm + OFF_P2);
    float*  BUF = sm + OFF_BUF;   // per-warp: TG[256] | SC[256]

    int s = blockIdx.x, tid = threadIdx.x;
    int w = tid >> 5, lane = tid & 31;
    int base = s * 64;

    #pragma unroll
    for (int it = 0; it < 8; it++) {           // KF,VF transpose (coalesced LDG)
        int idx = tid + it * 1024;
        int r = idx >> 7, c = idx & 127;
        KFt[c * 66 + r] = g_y[(base + r) * 384 + 128 + c];
        VFt[c * 68 + r] = g_y[(base + r) * 384 + 256 + c];
    }
    #pragma unroll
    for (int it = 0; it < 8; it++) {           // WK2 re-strided copy
        int idx = tid + it * 1024;
        int row = idx >> 6, c = idx & 63;
        WK2[row * 66 + c] = g_wk2[idx];
    }
    #pragma unroll
    for (int it = 0; it < 2; it++) {           // WV2 float4 re-strided copy
        int idx = tid + it * 1024;
        int row = idx >> 4, cq = idx & 15;
        *(float4*)&WV2[row * 68 + cq * 4] = *(const float4*)&g_wv2[row * 64 + cq * 4];
    }
    if (tid < 64) {
        W1B[tid] = make_float4(W1[tid * 2], W1[tid * 2 + 1], b1[tid], 0.f);
        P2[tid]  = *(const float2*)&pos[(base + tid) * 2];
    }

    // Q in registers: query i needs q[i][h*32+lane] per head (coalesced loads)
    float qreg[2][4];
    #pragma unroll
    for (int qi = 0; qi < 2; qi++) {
        int i = w + qi * 32;
        #pragma unroll
        for (int h = 0; h < 4; h++)
            qreg[qi][h] = g_y[(base + i) * 384 + h * 32 + lane];
    }
    __syncthreads();

    float* myTG = BUF + w * 512;        // T then G (same space)
    float* mySC = myTG + 256;
    int c0 = 2 * lane, c1 = c0 + 1;     // also j0, j1

    float4 wp0 = W1B[c0], wp1 = W1B[c1];
    float2 pj0 = P2[c0],  pj1 = P2[c1];

    #pragma unroll
    for (int qi = 0; qi < 2; qi++) {
        int i = w + qi * 32;
        float2 pi = P2[i];
        float dxj0 = pj0.x - pi.x, dyj0 = pj0.y - pi.y;
        float dxj1 = pj1.x - pi.x, dyj1 = pj1.y - pi.y;

        // ---- merged: t[h][c-pair] and qk-score[h][j-pair] over d (q via shfl) ----
        unsigned long long tacc[4], sacc[4];
        #pragma unroll
        for (int h = 0; h < 4; h++) { tacc[h] = 0ULL; sacc[h] = 0ULL; }
        #pragma unroll
        for (int h = 0; h < 4; h++) {
            float qh = qreg[qi][h];
            #pragma unroll 8
            for (int d = 0; d < 32; d++) {
                float qv = __shfl_sync(0xffffffffu, qh, d);
                unsigned long long qd = dup2(qv);
                int dd = h * 32 + d;
                unsigned long long kk = *(const unsigned long long*)&KFt[dd * 66 + c0];
                unsigned long long wk = *(const unsigned long long*)&WK2[dd * 66 + c0];
                ffma2(tacc[h], qd, wk);
                ffma2(sacc[h], qd, kk);
            }
        }
        // write t ([c][h] layout -> natural head-pairs), repack scores into head-pairs
        unsigned long long aj0_01, aj0_23, aj1_01, aj1_23;
        {
            float2 t0 = unpk2(tacc[0]), t1 = unpk2(tacc[1]);
            float2 t2 = unpk2(tacc[2]), t3 = unpk2(tacc[3]);
            *(float4*)&myTG[c0 * 4] = make_float4(t0.x, t1.x, t2.x, t3.x);
            *(float4*)&myTG[c1 * 4] = make_float4(t0.y, t1.y, t2.y, t3.y);
            float2 s0 = unpk2(sacc[0]), s1 = unpk2(sacc[1]);
            float2 s2 = unpk2(sacc[2]), s3 = unpk2(sacc[3]);
            aj0_01 = pk2(s0.x, s1.x); aj0_23 = pk2(s2.x, s3.x);
            aj1_01 = pk2(s0.y, s1.y); aj1_23 = pk2(s2.y, s3.y);
        }
        __syncwarp();

        // ---- rel-encoding contribution to scores (head-pair FFMA2) ----
        #pragma unroll 8
        for (int c = 0; c < 64; c++) {
            float4 wb = W1B[c];
            F4U tv; tv.f4 = *(const float4*)&myTG[c * 4];
            float h0 = fmaxf(fmaf(wb.x, dxj0, fmaf(wb.y, dyj0, wb.z)), 0.f);
            float h1 = fmaxf(fmaf(wb.x, dxj1, fmaf(wb.y, dyj1, wb.z)), 0.f);
            unsigned long long h0d = dup2(h0), h1d = dup2(h1);
            ffma2(aj0_01, tv.u[0], h0d);
            ffma2(aj0_23, tv.u[1], h0d);
            ffma2(aj1_01, tv.u[0], h1d);
            ffma2(aj1_23, tv.u[1], h1d);
        }
        __syncwarp();   // myTG (T) fully consumed by every lane before G overwrites

        // ---- softmax per head ----
        float a0[4], a1[4];
        {
            float2 u01j0 = unpk2(aj0_01), u23j0 = unpk2(aj0_23);
            float2 u01j1 = unpk2(aj1_01), u23j1 = unpk2(aj1_23);
            a0[0] = u01j0.x; a0[1] = u01j0.y; a0[2] = u23j0.x; a0[3] = u23j0.y;
            a1[0] = u01j1.x; a1[1] = u01j1.y; a1[2] = u23j1.x; a1[3] = u23j1.y;
        }
        #pragma unroll
        for (int h = 0; h < 4; h++) {
            float m = fmaxf(a0[h], a1[h]);
            #pragma unroll
            for (int off = 16; off; off >>= 1)
                m = fmaxf(m, __shfl_xor_sync(0xffffffffu, m, off));
            float e0 = __expf(a0[h] - m), e1 = __expf(a1[h] - m);
            float ss = e0 + e1;
            #pragma unroll
            for (int off = 16; off; off >>= 1)
                ss += __shfl_xor_sync(0xffffffffu, ss, off);
            float rinv = 1.f / ss;
            *(float2*)&mySC[h * 64 + c0] = make_float2(e0 * rinv, e1 * rinv);
        }
        __syncwarp();

        // ---- g[h][c-pair] = sum_j attn[h][j] * hid[j][c] ----
        {
            float g0[4] = {0, 0, 0, 0}, g1[4] = {0, 0, 0, 0};
            #pragma unroll 4
            for (int j = 0; j < 64; j++) {
                float2 pj = P2[j];
                float dx = pj.x - pi.x, dy = pj.y - pi.y;
                float h0 = fmaxf(fmaf(wp0.x, dx, fmaf(wp0.y, dy, wp0.z)), 0.f);
                float h1 = fmaxf(fmaf(wp1.x, dx, fmaf(wp1.y, dy, wp1.z)), 0.f);
                #pragma unroll
                for (int h = 0; h < 4; h++) {
                    float a = mySC[h * 64 + j];
                    g0[h] = fmaf(a, h0, g0[h]);
                    g1[h] = fmaf(a, h1, g1[h]);
                }
            }
            #pragma unroll
            for (int h = 0; h < 4; h++)
                *(float2*)&myTG[h * 64 + c0] = make_float2(g0[h], g1[h]);  // G
        }
        __syncwarp();

        // ---- ctx[i][h*32+lane] = attn@vf + g@Wv2^T (packed FFMA2) ----
        #pragma unroll
        for (int h = 0; h < 4; h++) {
            unsigned long long pacc = 0ULL;
            const float* vr = VFt + (h * 32 + lane) * 68;
            const float* ar = mySC + h * 64;
            #pragma unroll
            for (int jq = 0; jq < 16; jq++) {
                F4U av, vv;
                av.f4 = *(const float4*)&ar[jq * 4];
                vv.f4 = *(const float4*)&vr[jq * 4];
                ffma2(pacc, av.u[0], vv.u[0]);
                ffma2(pacc, av.u[1], vv.u[1]);
            }
            const float* wr = WV2 + (h * 32 + lane) * 68;
            const float* gr = myTG + h * 64;
            #pragma unroll
            for (int cq = 0; cq < 16; cq++) {
                F4U gv, wv;
                gv.f4 = *(const float4*)&gr[cq * 4];
                wv.f4 = *(const float4*)&wr[cq * 4];
                ffma2(pacc, gv.u[0], wv.u[0]);
                ffma2(pacc, gv.u[1], wv.u[1]);
            }
            float2 pr = unpk2(pacc);
            g_ctx[(base + i) * 128 + h * 32 + lane] = pr.x + pr.y;
        }
        __syncwarp();
    }
}

// ---------------- launch ----------------
extern "C" void kernel_launch(void* const* d_in, const int* in_sizes, int n_in,
                              void* d_out, int out_size)
{
    const float* node_features = (const float*)d_in[0];
    const float* positions     = (const float*)d_in[1];
    const float* W1            = (const float*)d_in[2];
    const float* b1            = (const float*)d_in[3];
    const float* W2            = (const float*)d_in[4];
    const float* b2            = (const float*)d_in[5];
    const float* in_proj_w     = (const float*)d_in[6];
    const float* in_proj_b     = (const float*)d_in[7];
    const float* out_w         = (const float*)d_in[8];
    const float* out_b         = (const float*)d_in[9];
    const float* proj_w        = (const float*)d_in[10];
    const float* proj_b        = (const float*)d_in[11];
    float* out = (float*)d_out;

    size_t attn_smem = (size_t)ATTN_SMEM_FLOATS * sizeof(float);
    cudaFuncSetAttribute(attn_kernel, cudaFuncAttributeMaxDynamicSharedMemorySize,
                         (int)attn_smem);

    prep_kernel<<<130, 256>>>(in_proj_w, in_proj_b, W2, b2, out_w, out_b, proj_w, proj_b);
    qkv_gemm<<<dim3(TOTAL / 128, 384 / 64), 256>>>(node_features, in_proj_w);
    attn_kernel<<<S_SCENES, 1024, attn_smem>>>(positions, W1, b1);
    out_gemm<<<dim3(TOTAL / 128, 128 / 64), 256>>>(node_features, proj_w, out);
}

// round 5
// speedup vs baseline: 1.0841x; 1.0008x over previous
#include <cuda_runtime.h>
#include <math.h>

#define S_SCENES 128
#define N_PED    64
#define HID      128
#define TOTAL    (S_SCENES * N_PED)   // 8192
#define QSCALE   0.17677669529663687f // 1/sqrt(32)

// ---------------- device scratch ----------------
__device__ float g_y[TOTAL * 384];    // q | kf | vf  (q pre-scaled)
__device__ float g_ctx[TOTAL * HID];  // attention context
__device__ float g_wk2[HID * 64];     // Wk @ W2
__device__ float g_wv2[HID * 64];     // Wv @ W2
__device__ float g_wco[HID * HID];    // P2 @ out_w
__device__ float g_bias384[384];      // [bq | bk+Wk@b2 | bv+Wv@b2]
__device__ float g_bco[HID];          // proj_b + P2 @ out_b

// ---------------- f32x2 helpers ----------------
__device__ __forceinline__ unsigned long long dup2(float x) {
    unsigned long long r;
    asm("mov.b64 %0, {%1, %1};" : "=l"(r) : "r"(__float_as_uint(x)));
    return r;
}
__device__ __forceinline__ unsigned long long pk2(float lo, float hi) {
    unsigned long long r;
    asm("mov.b64 %0, {%1, %2};" : "=l"(r) : "r"(__float_as_uint(lo)), "r"(__float_as_uint(hi)));
    return r;
}
__device__ __forceinline__ void ffma2(unsigned long long& d,
                                      unsigned long long a, unsigned long long b) {
    asm("fma.rn.f32x2 %0, %1, %2, %0;" : "+l"(d) : "l"(a), "l"(b));
}
__device__ __forceinline__ float2 unpk2(unsigned long long v) {
    unsigned lo, hi;
    asm("mov.b64 {%0, %1}, %2;" : "=r"(lo), "=r"(hi) : "l"(v));
    return make_float2(__uint_as_float(lo), __uint_as_float(hi));
}
union F4U { float4 f4; unsigned long long u[2]; float f[4]; };

// ---------------- K1: combine weights ----------------
__global__ void prep_kernel(const float* __restrict__ ipw,
                            const float* __restrict__ ipb,
                            const float* __restrict__ W2,
                            const float* __restrict__ b2,
                            const float* __restrict__ outw,
                            const float* __restrict__ outb,
                            const float* __restrict__ pw,
                            const float* __restrict__ pb)
{
    int idx = blockIdx.x * blockDim.x + threadIdx.x;
    if (idx < 384) {
        float v = ipb[idx];
        if (idx >= 128) {
            const float* wrow = ipw + idx * 128;
            float acc = 0.f;
            #pragma unroll 8
            for (int d = 0; d < 128; d++) acc += wrow[d] * b2[d];
            v += acc;
        }
        g_bias384[idx] = v;
        return;
    }
    int t = idx - 384;
    if (t < 8192) {
        int hd = t >> 6, c = t & 63;
        const float* wrow = ipw + (128 + hd) * 128;
        float acc = 0.f;
        #pragma unroll 8
        for (int d = 0; d < 128; d++) acc += wrow[d] * W2[d * 64 + c];
        g_wk2[t] = acc;
        return;
    }
    t -= 8192;
    if (t < 8192) {
        int hd = t >> 6, c = t & 63;
        const float* wrow = ipw + (256 + hd) * 128;
        float acc = 0.f;
        #pragma unroll 8
        for (int d = 0; d < 128; d++) acc += wrow[d] * W2[d * 64 + c];
        g_wv2[t] = acc;
        return;
    }
    t -= 8192;
    if (t < 16384) {
        int n = t >> 7, k = t & 127;
        const float* p2 = pw + n * 256 + 128;
        float acc = 0.f;
        #pragma unroll 8
        for (int d = 0; d < 128; d++) acc += p2[d] * outw[d * 128 + k];
        g_wco[t] = acc;
        return;
    }
    t -= 16384;
    if (t < 128) {
        const float* p2 = pw + t * 256 + 128;
        float acc = pb[t];
        #pragma unroll 8
        for (int d = 0; d < 128; d++) acc += p2[d] * outb[d];
        g_bco[t] = acc;
    }
}

// ---------------- GEMMs: R2 config (128x64 tile, BK=32, 256 thr, 8x4 microtile) ----------------
#define AS_P 132
#define BS_P 68

__global__ void __launch_bounds__(256) qkv_gemm(const float* __restrict__ X,
                                                const float* __restrict__ W)
{
    __shared__ float As[32][AS_P];   // [k][m]
    __shared__ float Bs[32][BS_P];   // [k][n]
    int m0 = blockIdx.x * 128, n0 = blockIdx.y * 64;
    int tid = threadIdx.x, tx = tid & 15, ty = tid >> 4;

    unsigned long long acc[4][4];
    #pragma unroll
    for (int r = 0; r < 4; r++)
        #pragma unroll
        for (int c = 0; c < 4; c++) acc[r][c] = 0ULL;

    float4 pa[4], pb[2];
    int rowA[4], kqA[4], rowB[2], kqB[2];
    #pragma unroll
    for (int i = 0; i < 4; i++) { int idx = tid + i * 256; rowA[i] = idx >> 3; kqA[i] = idx & 7; }
    #pragma unroll
    for (int i = 0; i < 2; i++) { int idx = tid + i * 256; rowB[i] = idx >> 3; kqB[i] = idx & 7; }

    #pragma unroll
    for (int i = 0; i < 4; i++) pa[i] = *(const float4*)&X[(m0 + rowA[i]) * 128 + kqA[i] * 4];
    #pragma unroll
    for (int i = 0; i < 2; i++) pb[i] = *(const float4*)&W[(n0 + rowB[i]) * 128 + kqB[i] * 4];

    for (int kc = 0; kc < 4; kc++) {
        #pragma unroll
        for (int i = 0; i < 4; i++) {
            As[kqA[i] * 4 + 0][rowA[i]] = pa[i].x;
            As[kqA[i] * 4 + 1][rowA[i]] = pa[i].y;
            As[kqA[i] * 4 + 2][rowA[i]] = pa[i].z;
            As[kqA[i] * 4 + 3][rowA[i]] = pa[i].w;
        }
        #pragma unroll
        for (int i = 0; i < 2; i++) {
            Bs[kqB[i] * 4 + 0][rowB[i]] = pb[i].x;
            Bs[kqB[i] * 4 + 1][rowB[i]] = pb[i].y;
            Bs[kqB[i] * 4 + 2][rowB[i]] = pb[i].z;
            Bs[kqB[i] * 4 + 3][rowB[i]] = pb[i].w;
        }
        __syncthreads();
        if (kc < 3) {
            int k0 = (kc + 1) * 32;
            #pragma unroll
            for (int i = 0; i < 4; i++) pa[i] = *(const float4*)&X[(m0 + rowA[i]) * 128 + k0 + kqA[i] * 4];
            #pragma unroll
            for (int i = 0; i < 2; i++) pb[i] = *(const float4*)&W[(n0 + rowB[i]) * 128 + k0 + kqB[i] * 4];
        }
        #pragma unroll
        for (int k = 0; k < 32; k++) {
            F4U a0, a1, b;
            a0.f4 = *(const float4*)&As[k][ty * 8];
            a1.f4 = *(const float4*)&As[k][ty * 8 + 4];
            b.f4  = *(const float4*)&Bs[k][tx * 4];
            unsigned long long bd[4];
            #pragma unroll
            for (int c = 0; c < 4; c++) bd[c] = dup2(b.f[c]);
            #pragma unroll
            for (int c = 0; c < 4; c++) {
                ffma2(acc[0][c], a0.u[0], bd[c]);
                ffma2(acc[1][c], a0.u[1], bd[c]);
                ffma2(acc[2][c], a1.u[0], bd[c]);
                ffma2(acc[3][c], a1.u[1], bd[c]);
            }
        }
        __syncthreads();
    }
    float scale = (n0 < 128) ? QSCALE : 1.0f;
    int n = n0 + tx * 4;
    float4 b4 = *(const float4*)&g_bias384[n];
    #pragma unroll
    for (int r2 = 0; r2 < 4; r2++) {
        float2 p0 = unpk2(acc[r2][0]), p1 = unpk2(acc[r2][1]);
        float2 p2 = unpk2(acc[r2][2]), p3 = unpk2(acc[r2][3]);
        int m = m0 + ty * 8 + r2 * 2;
        float4 lo = make_float4((p0.x + b4.x) * scale, (p1.x + b4.y) * scale,
                                (p2.x + b4.z) * scale, (p3.x + b4.w) * scale);
        float4 hi = make_float4((p0.y + b4.x) * scale, (p1.y + b4.y) * scale,
                                (p2.y + b4.z) * scale, (p3.y + b4.w) * scale);
        *(float4*)&g_y[m * 384 + n] = lo;
        *(float4*)&g_y[(m + 1) * 384 + n] = hi;
    }
}

__global__ void __launch_bounds__(256) out_gemm(const float* __restrict__ X,
                                                const float* __restrict__ PW,
                                                float* __restrict__ OUT)
{
    __shared__ float As[32][AS_P];
    __shared__ float Bs[32][BS_P];
    int m0 = blockIdx.x * 128, n0 = blockIdx.y * 64;
    int tid = threadIdx.x, tx = tid & 15, ty = tid >> 4;

    unsigned long long acc[4][4];
    #pragma unroll
    for (int r = 0; r < 4; r++)
        #pragma unroll
        for (int c = 0; c < 4; c++) acc[r][c] = 0ULL;

    float4 pa[4], pb[2];
    int rowA[4], kqA[4], rowB[2], kqB[2];
    #pragma unroll
    for (int i = 0; i < 4; i++) { int idx = tid + i * 256; rowA[i] = idx >> 3; kqA[i] = idx & 7; }
    #pragma unroll
    for (int i = 0; i < 2; i++) { int idx = tid + i * 256; rowB[i] = idx >> 3; kqB[i] = idx & 7; }

    #pragma unroll
    for (int i = 0; i < 4; i++) pa[i] = *(const float4*)&X[(m0 + rowA[i]) * 128 + kqA[i] * 4];
    #pragma unroll
    for (int i = 0; i < 2; i++) pb[i] = *(const float4*)&PW[(n0 + rowB[i]) * 256 + kqB[i] * 4];

    for (int kc = 0; kc < 8; kc++) {
        #pragma unroll
        for (int i = 0; i < 4; i++) {
            As[kqA[i] * 4 + 0][rowA[i]] = pa[i].x;
            As[kqA[i] * 4 + 1][rowA[i]] = pa[i].y;
            As[kqA[i] * 4 + 2][rowA[i]] = pa[i].z;
            As[kqA[i] * 4 + 3][rowA[i]] = pa[i].w;
        }
        #pragma unroll
        for (int i = 0; i < 2; i++) {
            Bs[kqB[i] * 4 + 0][rowB[i]] = pb[i].x;
            Bs[kqB[i] * 4 + 1][rowB[i]] = pb[i].y;
            Bs[kqB[i] * 4 + 2][rowB[i]] = pb[i].z;
            Bs[kqB[i] * 4 + 3][rowB[i]] = pb[i].w;
        }
        __syncthreads();
        if (kc < 7) {
            int knext = kc + 1;
            int kcol = (knext & 3) * 32;
            if (knext < 4) {
                #pragma unroll
                for (int i = 0; i < 4; i++) pa[i] = *(const float4*)&X[(m0 + rowA[i]) * 128 + kcol + kqA[i] * 4];
                #pragma unroll
                for (int i = 0; i < 2; i++) pb[i] = *(const float4*)&PW[(n0 + rowB[i]) * 256 + kcol + kqB[i] * 4];
            } else {
                #pragma unroll
                for (int i = 0; i < 4; i++) pa[i] = *(const float4*)&g_ctx[(m0 + rowA[i]) * 128 + kcol + kqA[i] * 4];
                #pragma unroll
                for (int i = 0; i < 2; i++) pb[i] = *(const float4*)&g_wco[(n0 + rowB[i]) * 128 + kcol + kqB[i] * 4];
            }
        }
        #pragma unroll
        for (int k = 0; k < 32; k++) {
            F4U a0, a1, b;
            a0.f4 = *(const float4*)&As[k][ty * 8];
            a1.f4 = *(const float4*)&As[k][ty * 8 + 4];
            b.f4  = *(const float4*)&Bs[k][tx * 4];
            unsigned long long bd[4];
            #pragma unroll
            for (int c = 0; c < 4; c++) bd[c] = dup2(b.f[c]);
            #pragma unroll
            for (int c = 0; c < 4; c++) {
                ffma2(acc[0][c], a0.u[0], bd[c]);
                ffma2(acc[1][c], a0.u[1], bd[c]);
                ffma2(acc[2][c], a1.u[0], bd[c]);
                ffma2(acc[3][c], a1.u[1], bd[c]);
            }
        }
        __syncthreads();
    }
    int n = n0 + tx * 4;
    float4 b4 = *(const float4*)&g_bco[n];
    #pragma unroll
    for (int r2 = 0; r2 < 4; r2++) {
        float2 p0 = unpk2(acc[r2][0]), p1 = unpk2(acc[r2][1]);
        float2 p2 = unpk2(acc[r2][2]), p3 = unpk2(acc[r2][3]);
        int m = m0 + ty * 8 + r2 * 2;
        float4 lo = make_float4(p0.x + b4.x, p1.x + b4.y, p2.x + b4.z, p3.x + b4.w);
        float4 hi = make_float4(p0.y + b4.x, p1.y + b4.y, p2.y + b4.z, p3.y + b4.w);
        *(float4*)&OUT[m * 128 + n] = lo;
        *(float4*)&OUT[(m + 1) * 128 + n] = hi;
    }
}

// ---------------- K3: attention, 1024 threads, 32 warps x 2 queries ----------------
// smem floats: KFt[128*66]=8448 | WK2[128*66]=8448 | VFt[128*68]=8704 | WV2[128*68]=8704 |
//              W1B[64*4]=256 | P2[64*2]=128 | per-warp TG+SC: 32*512=16384  => 51072 (199.5KB)
#define OFF_WK2  8448
#define OFF_VF   16896
#define OFF_WV2  25600
#define OFF_W1B  34304
#define OFF_P2   34560
#define OFF_BUF  34688
#define ATTN_SMEM_FLOATS (34688 + 32 * 512)

__global__ void __launch_bounds__(1024) attn_kernel(const float* __restrict__ pos,
                                                    const float* __restrict__ W1,
                                                    const float* __restrict__ b1)
{
    extern __shared__ float sm[];
    float*  KFt = sm;             // [d][j]  stride 66
    float*  WK2 = sm + OFF_WK2;   // [d][c]  stride 66
    float*  VFt = sm + OFF_VF;    // [vd][j] stride 68
    float*  WV2 = sm + OFF_WV2;   // [vd][c] stride 68
    float4* W1B = (float4*)(sm + OFF_W1B);
    float2* P2  = (float2*)(sm + OFF_P2);
    float*  BUF = sm + OFF_BUF;   // per-warp: TG[256] | SC[256]

    int s = blockIdx.x, tid = threadIdx.x;
    int w = tid >> 5, lane = tid & 31;
    int base = s * 64;

    #pragma unroll
    for (int it = 0; it < 8; it++) {           // KF,VF transpose (coalesced LDG)
        int idx = tid + it * 1024;
        int r = idx >> 7, c = idx & 127;
        KFt[c * 66 + r] = g_y[(base + r) * 384 + 128 + c];
        VFt[c * 68 + r] = g_y[(base + r) * 384 + 256 + c];
    }
    #pragma unroll
    for (int it = 0; it < 8; it++) {           // WK2 re-strided copy
        int idx = tid + it * 1024;
        int row = idx >> 6, c = idx & 63;
        WK2[row * 66 + c] = g_wk2[idx];
    }
    #pragma unroll
    for (int it = 0; it < 2; it++) {           // WV2 float4 re-strided copy
        int idx = tid + it * 1024;
        int row = idx >> 4, cq = idx & 15;
        *(float4*)&WV2[row * 68 + cq * 4] = *(const float4*)&g_wv2[row * 64 + cq * 4];
    }
    if (tid < 64) {
        W1B[tid] = make_float4(W1[tid * 2], W1[tid * 2 + 1], b1[tid], 0.f);
        P2[tid]  = *(const float2*)&pos[(base + tid) * 2];
    }

    // Q in registers: query i needs q[i][h*32+lane] per head (coalesced loads)
    float qreg[2][4];
    #pragma unroll
    for (int qi = 0; qi < 2; qi++) {
        int i = w + qi * 32;
        #pragma unroll
        for (int h = 0; h < 4; h++)
            qreg[qi][h] = g_y[(base + i) * 384 + h * 32 + lane];
    }
    __syncthreads();

    float* myTG = BUF + w * 512;        // T then G (same space)
    float* mySC = myTG + 256;
    int c0 = 2 * lane, c1 = c0 + 1;     // also j0, j1

    float4 wp0 = W1B[c0], wp1 = W1B[c1];
    float2 pj0 = P2[c0],  pj1 = P2[c1];

    #pragma unroll
    for (int qi = 0; qi < 2; qi++) {
        int i = w + qi * 32;
        float2 pi = P2[i];
        float dxj0 = pj0.x - pi.x, dyj0 = pj0.y - pi.y;
        float dxj1 = pj1.x - pi.x, dyj1 = pj1.y - pi.y;

        // ---- merged: t[h][c-pair] and qk-score[h][j-pair] over d (q via shfl) ----
        unsigned long long tacc[4], sacc[4];
        #pragma unroll
        for (int h = 0; h < 4; h++) { tacc[h] = 0ULL; sacc[h] = 0ULL; }
        #pragma unroll
        for (int h = 0; h < 4; h++) {
            float qh = qreg[qi][h];
            #pragma unroll 8
            for (int d = 0; d < 32; d++) {
                float qv = __shfl_sync(0xffffffffu, qh, d);
                unsigned long long qd = dup2(qv);
                int dd = h * 32 + d;
                unsigned long long kk = *(const unsigned long long*)&KFt[dd * 66 + c0];
                unsigned long long wk = *(const unsigned long long*)&WK2[dd * 66 + c0];
                ffma2(tacc[h], qd, wk);
                ffma2(sacc[h], qd, kk);
            }
        }
        // write t ([c][h] layout -> natural head-pairs), repack scores into head-pairs
        unsigned long long aj0_01, aj0_23, aj1_01, aj1_23;
        {
            float2 t0 = unpk2(tacc[0]), t1 = unpk2(tacc[1]);
            float2 t2 = unpk2(tacc[2]), t3 = unpk2(tacc[3]);
            *(float4*)&myTG[c0 * 4] = make_float4(t0.x, t1.x, t2.x, t3.x);
            *(float4*)&myTG[c1 * 4] = make_float4(t0.y, t1.y, t2.y, t3.y);
            float2 s0 = unpk2(sacc[0]), s1 = unpk2(sacc[1]);
            float2 s2 = unpk2(sacc[2]), s3 = unpk2(sacc[3]);
            aj0_01 = pk2(s0.x, s1.x); aj0_23 = pk2(s2.x, s3.x);
            aj1_01 = pk2(s0.y, s1.y); aj1_23 = pk2(s2.y, s3.y);
        }
        __syncwarp();

        // ---- rel-encoding contribution to scores (head-pair FFMA2) ----
        #pragma unroll 8
        for (int c = 0; c < 64; c++) {
            float4 wb = W1B[c];
            F4U tv; tv.f4 = *(const float4*)&myTG[c * 4];
            float h0 = fmaxf(fmaf(wb.x, dxj0, fmaf(wb.y, dyj0, wb.z)), 0.f);
            float h1 = fmaxf(fmaf(wb.x, dxj1, fmaf(wb.y, dyj1, wb.z)), 0.f);
            unsigned long long h0d = dup2(h0), h1d = dup2(h1);
            ffma2(aj0_01, tv.u[0], h0d);
            ffma2(aj0_23, tv.u[1], h0d);
            ffma2(aj1_01, tv.u[0], h1d);
            ffma2(aj1_23, tv.u[1], h1d);
        }
        __syncwarp();   // myTG (T) fully consumed by every lane before G overwrites

        // ---- softmax per head ----
        float a0[4], a1[4];
        {
            float2 u01j0 = unpk2(aj0_01), u23j0 = unpk2(aj0_23);
            float2 u01j1 = unpk2(aj1_01), u23j1 = unpk2(aj1_23);
            a0[0] = u01j0.x; a0[1] = u01j0.y; a0[2] = u23j0.x; a0[3] = u23j0.y;
            a1[0] = u01j1.x; a1[1] = u01j1.y; a1[2] = u23j1.x; a1[3] = u23j1.y;
        }
        #pragma unroll
        for (int h = 0; h < 4; h++) {
            float m = fmaxf(a0[h], a1[h]);
            #pragma unroll
            for (int off = 16; off; off >>= 1)
                m = fmaxf(m, __shfl_xor_sync(0xffffffffu, m, off));
            float e0 = __expf(a0[h] - m), e1 = __expf(a1[h] - m);
            float ss = e0 + e1;
            #pragma unroll
            for (int off = 16; off; off >>= 1)
                ss += __shfl_xor_sync(0xffffffffu, ss, off);
            float rinv = 1.f / ss;
            *(float2*)&mySC[h * 64 + c0] = make_float2(e0 * rinv, e1 * rinv);
        }
        __syncwarp();

        // ---- g[h][c-pair] = sum_j attn[h][j] * hid[j][c] ----
        {
            float g0[4] = {0, 0, 0, 0}, g1[4] = {0, 0, 0, 0};
            #pragma unroll 4
            for (int j = 0; j < 64; j++) {
                float2 pj = P2[j];
                float dx = pj.x - pi.x, dy = pj.y - pi.y;
                float h0 = fmaxf(fmaf(wp0.x, dx, fmaf(wp0.y, dy, wp0.z)), 0.f);
                float h1 = fmaxf(fmaf(wp1.x, dx, fmaf(wp1.y, dy, wp1.z)), 0.f);
                #pragma unroll
                for (int h = 0; h < 4; h++) {
                    float a = mySC[h * 64 + j];
                    g0[h] = fmaf(a, h0, g0[h]);
                    g1[h] = fmaf(a, h1, g1[h]);
                }
            }
            #pragma unroll
            for (int h = 0; h < 4; h++)
                *(float2*)&myTG[h * 64 + c0] = make_float2(g0[h], g1[h]);  // G
        }
        __syncwarp();

        // ---- ctx[i][h*32+lane] = attn@vf + g@Wv2^T (packed FFMA2) ----
        #pragma unroll
        for (int h = 0; h < 4; h++) {
            unsigned long long pacc = 0ULL;
            const float* vr = VFt + (h * 32 + lane) * 68;
            const float* ar = mySC + h * 64;
            #pragma unroll
            for (int jq = 0; jq < 16; jq++) {
                F4U av, vv;
                av.f4 = *(const float4*)&ar[jq * 4];
                vv.f4 = *(const float4*)&vr[jq * 4];
                ffma2(pacc, av.u[0], vv.u[0]);
                ffma2(pacc, av.u[1], vv.u[1]);
            }
            const float* wr = WV2 + (h * 32 + lane) * 68;
            const float* gr = myTG + h * 64;
            #pragma unroll
            for (int cq = 0; cq < 16; cq++) {
                F4U gv, wv;
                gv.f4 = *(const float4*)&gr[cq * 4];
                wv.f4 = *(const float4*)&wr[cq * 4];
                ffma2(pacc, gv.u[0], wv.u[0]);
                ffma2(pacc, gv.u[1], wv.u[1]);
            }
            float2 pr = unpk2(pacc);
            g_ctx[(base + i) * 128 + h * 32 + lane] = pr.x + pr.y;
        }
        __syncwarp();
    }
}

// ---------------- launch ----------------
extern "C" void kernel_launch(void* const* d_in, const int* in_sizes, int n_in,
                              void* d_out, int out_size)
{
    const float* node_features = (const float*)d_in[0];
    const float* positions     = (const float*)d_in[1];
    const float* W1            = (const float*)d_in[2];
    const float* b1            = (const float*)d_in[3];
    const float* W2            = (const float*)d_in[4];
    const float* b2            = (const float*)d_in[5];
    const float* in_proj_w     = (const float*)d_in[6];
    const float* in_proj_b     = (const float*)d_in[7];
    const float* out_w         = (const float*)d_in[8];
    const float* out_b         = (const float*)d_in[9];
    const float* proj_w        = (const float*)d_in[10];
    const float* proj_b        = (const float*)d_in[11];
    float* out = (float*)d_out;

    size_t attn_smem = (size_t)ATTN_SMEM_FLOATS * sizeof(float);
    cudaFuncSetAttribute(attn_kernel, cudaFuncAttributeMaxDynamicSharedMemorySize,
                         (int)attn_smem);

    prep_kernel<<<130, 256>>>(in_proj_w, in_proj_b, W2, b2, out_w, out_b, proj_w, proj_b);
    qkv_gemm<<<dim3(TOTAL / 128, 384 / 64), 256>>>(node_features, in_proj_w);
    attn_kernel<<<S_SCENES, 1024, attn_smem>>>(positions, W1, b1);
    out_gemm<<<dim3(TOTAL / 128, 128 / 64), 256>>>(node_features, proj_w, out);
}

// round 6
// speedup vs baseline: 1.2257x; 1.1306x over previous
#include <cuda_runtime.h>
#include <math.h>

#define S_SCENES 128
#define N_PED    64
#define HID      128
#define TOTAL    (S_SCENES * N_PED)   // 8192
#define QSCALE   0.17677669529663687f // 1/sqrt(32)

// ---------------- device scratch ----------------
__device__ float g_y[TOTAL * 384];    // q | kf | vf  (q pre-scaled)
__device__ float g_ctx[TOTAL * HID];  // attention context
__device__ float g_wk2[HID * 64];     // Wk @ W2
__device__ float g_wv2[HID * 64];     // Wv @ W2
__device__ float g_wco[HID * HID];    // P2 @ out_w
__device__ float g_bias384[384];      // [bq | bk+Wk@b2 | bv+Wv@b2]
__device__ float g_bco[HID];          // proj_b + P2 @ out_b

// ---------------- f32x2 helpers ----------------
__device__ __forceinline__ unsigned long long dup2(float x) {
    unsigned long long r;
    asm("mov.b64 %0, {%1, %1};" : "=l"(r) : "r"(__float_as_uint(x)));
    return r;
}
__device__ __forceinline__ unsigned long long pk2(float lo, float hi) {
    unsigned long long r;
    asm("mov.b64 %0, {%1, %2};" : "=l"(r) : "r"(__float_as_uint(lo)), "r"(__float_as_uint(hi)));
    return r;
}
__device__ __forceinline__ void ffma2(unsigned long long& d,
                                      unsigned long long a, unsigned long long b) {
    asm("fma.rn.f32x2 %0, %1, %2, %0;" : "+l"(d) : "l"(a), "l"(b));
}
__device__ __forceinline__ float2 unpk2(unsigned long long v) {
    unsigned lo, hi;
    asm("mov.b64 {%0, %1}, %2;" : "=r"(lo), "=r"(hi) : "l"(v));
    return make_float2(__uint_as_float(lo), __uint_as_float(hi));
}
union F4U { float4 f4; unsigned long long u[2]; float f[4]; };

// ---------------- K1: combine weights ----------------
__global__ void prep_kernel(const float* __restrict__ ipw,
                            const float* __restrict__ ipb,
                            const float* __restrict__ W2,
                            const float* __restrict__ b2,
                            const float* __restrict__ outw,
                            const float* __restrict__ outb,
                            const float* __restrict__ pw,
                            const float* __restrict__ pb)
{
    int idx = blockIdx.x * blockDim.x + threadIdx.x;
    if (idx < 384) {
        float v = ipb[idx];
        if (idx >= 128) {
            const float* wrow = ipw + idx * 128;
            float acc = 0.f;
            #pragma unroll 8
            for (int d = 0; d < 128; d++) acc += wrow[d] * b2[d];
            v += acc;
        }
        g_bias384[idx] = v;
        return;
    }
    int t = idx - 384;
    if (t < 8192) {
        int hd = t >> 6, c = t & 63;
        const float* wrow = ipw + (128 + hd) * 128;
        float acc = 0.f;
        #pragma unroll 8
        for (int d = 0; d < 128; d++) acc += wrow[d] * W2[d * 64 + c];
        g_wk2[t] = acc;
        return;
    }
    t -= 8192;
    if (t < 8192) {
        int hd = t >> 6, c = t & 63;
        const float* wrow = ipw + (256 + hd) * 128;
        float acc = 0.f;
        #pragma unroll 8
        for (int d = 0; d < 128; d++) acc += wrow[d] * W2[d * 64 + c];
        g_wv2[t] = acc;
        return;
    }
    t -= 8192;
    if (t < 16384) {
        int n = t >> 7, k = t & 127;
        const float* p2 = pw + n * 256 + 128;
        float acc = 0.f;
        #pragma unroll 8
        for (int d = 0; d < 128; d++) acc += p2[d] * outw[d * 128 + k];
        g_wco[t] = acc;
        return;
    }
    t -= 16384;
    if (t < 128) {
        const float* p2 = pw + t * 256 + 128;
        float acc = pb[t];
        #pragma unroll 8
        for (int d = 0; d < 128; d++) acc += p2[d] * outb[d];
        g_bco[t] = acc;
    }
}

// ---------------- GEMMs: proven config (128x64 tile, BK=32, 256 thr, 8x4 micro) ----------------
#define AS_P 132
#define BS_P 68

__global__ void __launch_bounds__(256) qkv_gemm(const float* __restrict__ X,
                                                const float* __restrict__ W)
{
    __shared__ float As[32][AS_P];
    __shared__ float Bs[32][BS_P];
    int m0 = blockIdx.x * 128, n0 = blockIdx.y * 64;
    int tid = threadIdx.x, tx = tid & 15, ty = tid >> 4;

    unsigned long long acc[4][4];
    #pragma unroll
    for (int r = 0; r < 4; r++)
        #pragma unroll
        for (int c = 0; c < 4; c++) acc[r][c] = 0ULL;

    float4 pa[4], pb[2];
    int rowA[4], kqA[4], rowB[2], kqB[2];
    #pragma unroll
    for (int i = 0; i < 4; i++) { int idx = tid + i * 256; rowA[i] = idx >> 3; kqA[i] = idx & 7; }
    #pragma unroll
    for (int i = 0; i < 2; i++) { int idx = tid + i * 256; rowB[i] = idx >> 3; kqB[i] = idx & 7; }

    #pragma unroll
    for (int i = 0; i < 4; i++) pa[i] = *(const float4*)&X[(m0 + rowA[i]) * 128 + kqA[i] * 4];
    #pragma unroll
    for (int i = 0; i < 2; i++) pb[i] = *(const float4*)&W[(n0 + rowB[i]) * 128 + kqB[i] * 4];

    for (int kc = 0; kc < 4; kc++) {
        #pragma unroll
        for (int i = 0; i < 4; i++) {
            As[kqA[i] * 4 + 0][rowA[i]] = pa[i].x;
            As[kqA[i] * 4 + 1][rowA[i]] = pa[i].y;
            As[kqA[i] * 4 + 2][rowA[i]] = pa[i].z;
            As[kqA[i] * 4 + 3][rowA[i]] = pa[i].w;
        }
        #pragma unroll
        for (int i = 0; i < 2; i++) {
            Bs[kqB[i] * 4 + 0][rowB[i]] = pb[i].x;
            Bs[kqB[i] * 4 + 1][rowB[i]] = pb[i].y;
            Bs[kqB[i] * 4 + 2][rowB[i]] = pb[i].z;
            Bs[kqB[i] * 4 + 3][rowB[i]] = pb[i].w;
        }
        __syncthreads();
        if (kc < 3) {
            int k0 = (kc + 1) * 32;
            #pragma unroll
            for (int i = 0; i < 4; i++) pa[i] = *(const float4*)&X[(m0 + rowA[i]) * 128 + k0 + kqA[i] * 4];
            #pragma unroll
            for (int i = 0; i < 2; i++) pb[i] = *(const float4*)&W[(n0 + rowB[i]) * 128 + k0 + kqB[i] * 4];
        }
        #pragma unroll
        for (int k = 0; k < 32; k++) {
            F4U a0, a1, b;
            a0.f4 = *(const float4*)&As[k][ty * 8];
            a1.f4 = *(const float4*)&As[k][ty * 8 + 4];
            b.f4  = *(const float4*)&Bs[k][tx * 4];
            unsigned long long bd[4];
            #pragma unroll
            for (int c = 0; c < 4; c++) bd[c] = dup2(b.f[c]);
            #pragma unroll
            for (int c = 0; c < 4; c++) {
                ffma2(acc[0][c], a0.u[0], bd[c]);
                ffma2(acc[1][c], a0.u[1], bd[c]);
                ffma2(acc[2][c], a1.u[0], bd[c]);
                ffma2(acc[3][c], a1.u[1], bd[c]);
            }
        }
        __syncthreads();
    }
    float scale = (n0 < 128) ? QSCALE : 1.0f;
    int n = n0 + tx * 4;
    float4 b4 = *(const float4*)&g_bias384[n];
    #pragma unroll
    for (int r2 = 0; r2 < 4; r2++) {
        float2 p0 = unpk2(acc[r2][0]), p1 = unpk2(acc[r2][1]);
        float2 p2 = unpk2(acc[r2][2]), p3 = unpk2(acc[r2][3]);
        int m = m0 + ty * 8 + r2 * 2;
        float4 lo = make_float4((p0.x + b4.x) * scale, (p1.x + b4.y) * scale,
                                (p2.x + b4.z) * scale, (p3.x + b4.w) * scale);
        float4 hi = make_float4((p0.y + b4.x) * scale, (p1.y + b4.y) * scale,
                                (p2.y + b4.z) * scale, (p3.y + b4.w) * scale);
        *(float4*)&g_y[m * 384 + n] = lo;
        *(float4*)&g_y[(m + 1) * 384 + n] = hi;
    }
}

__global__ void __launch_bounds__(256) out_gemm(const float* __restrict__ X,
                                                const float* __restrict__ PW,
                                                float* __restrict__ OUT)
{
    __shared__ float As[32][AS_P];
    __shared__ float Bs[32][BS_P];
    int m0 = blockIdx.x * 128, n0 = blockIdx.y * 64;
    int tid = threadIdx.x, tx = tid & 15, ty = tid >> 4;

    unsigned long long acc[4][4];
    #pragma unroll
    for (int r = 0; r < 4; r++)
        #pragma unroll
        for (int c = 0; c < 4; c++) acc[r][c] = 0ULL;

    float4 pa[4], pb[2];
    int rowA[4], kqA[4], rowB[2], kqB[2];
    #pragma unroll
    for (int i = 0; i < 4; i++) { int idx = tid + i * 256; rowA[i] = idx >> 3; kqA[i] = idx & 7; }
    #pragma unroll
    for (int i = 0; i < 2; i++) { int idx = tid + i * 256; rowB[i] = idx >> 3; kqB[i] = idx & 7; }

    #pragma unroll
    for (int i = 0; i < 4; i++) pa[i] = *(const float4*)&X[(m0 + rowA[i]) * 128 + kqA[i] * 4];
    #pragma unroll
    for (int i = 0; i < 2; i++) pb[i] = *(const float4*)&PW[(n0 + rowB[i]) * 256 + kqB[i] * 4];

    for (int kc = 0; kc < 8; kc++) {
        #pragma unroll
        for (int i = 0; i < 4; i++) {
            As[kqA[i] * 4 + 0][rowA[i]] = pa[i].x;
            As[kqA[i] * 4 + 1][rowA[i]] = pa[i].y;
            As[kqA[i] * 4 + 2][rowA[i]] = pa[i].z;
            As[kqA[i] * 4 + 3][rowA[i]] = pa[i].w;
        }
        #pragma unroll
        for (int i = 0; i < 2; i++) {
            Bs[kqB[i] * 4 + 0][rowB[i]] = pb[i].x;
            Bs[kqB[i] * 4 + 1][rowB[i]] = pb[i].y;
            Bs[kqB[i] * 4 + 2][rowB[i]] = pb[i].z;
            Bs[kqB[i] * 4 + 3][rowB[i]] = pb[i].w;
        }
        __syncthreads();
        if (kc < 7) {
            int knext = kc + 1;
            int kcol = (knext & 3) * 32;
            if (knext < 4) {
                #pragma unroll
                for (int i = 0; i < 4; i++) pa[i] = *(const float4*)&X[(m0 + rowA[i]) * 128 + kcol + kqA[i] * 4];
                #pragma unroll
                for (int i = 0; i < 2; i++) pb[i] = *(const float4*)&PW[(n0 + rowB[i]) * 256 + kcol + kqB[i] * 4];
            } else {
                #pragma unroll
                for (int i = 0; i < 4; i++) pa[i] = *(const float4*)&g_ctx[(m0 + rowA[i]) * 128 + kcol + kqA[i] * 4];
                #pragma unroll
                for (int i = 0; i < 2; i++) pb[i] = *(const float4*)&g_wco[(n0 + rowB[i]) * 128 + kcol + kqB[i] * 4];
            }
        }
        #pragma unroll
        for (int k = 0; k < 32; k++) {
            F4U a0, a1, b;
            a0.f4 = *(const float4*)&As[k][ty * 8];
            a1.f4 = *(const float4*)&As[k][ty * 8 + 4];
            b.f4  = *(const float4*)&Bs[k][tx * 4];
            unsigned long long bd[4];
            #pragma unroll
            for (int c = 0; c < 4; c++) bd[c] = dup2(b.f[c]);
            #pragma unroll
            for (int c = 0; c < 4; c++) {
                ffma2(acc[0][c], a0.u[0], bd[c]);
                ffma2(acc[1][c], a0.u[1], bd[c]);
                ffma2(acc[2][c], a1.u[0], bd[c]);
                ffma2(acc[3][c], a1.u[1], bd[c]);
            }
        }
        __syncthreads();
    }
    int n = n0 + tx * 4;
    float4 b4 = *(const float4*)&g_bco[n];
    #pragma unroll
    for (int r2 = 0; r2 < 4; r2++) {
        float2 p0 = unpk2(acc[r2][0]), p1 = unpk2(acc[r2][1]);
        float2 p2 = unpk2(acc[r2][2]), p3 = unpk2(acc[r2][3]);
        int m = m0 + ty * 8 + r2 * 2;
        float4 lo = make_float4(p0.x + b4.x, p1.x + b4.y, p2.x + b4.z, p3.x + b4.w);
        float4 hi = make_float4(p0.y + b4.x, p1.y + b4.y, p2.y + b4.z, p3.y + b4.w);
        *(float4*)&OUT[m * 128 + n] = lo;
        *(float4*)&OUT[(m + 1) * 128 + n] = hi;
    }
}

// ---------------- K3: attention, 512 threads, 16 warps, 2 rounds x query-pair ----------------
// smem floats: KFt[128*66]=8448 | WK2[128*66]=8448 | VFt[128*68]=8704 | WV2[128*68]=8704 |
//              W1B[256] | P2[128] | BUF 16*1024=16384  => 51072 floats (199.5 KB)
#define OFF_WK2  8448
#define OFF_VF   16896
#define OFF_WV2  25600
#define OFF_W1B  34304
#define OFF_P2   34560
#define OFF_BUF  34688
#define ATTN_SMEM_FLOATS (34688 + 16 * 1024)

__global__ void __launch_bounds__(512) attn_kernel(const float* __restrict__ pos,
                                                   const float* __restrict__ W1,
                                                   const float* __restrict__ b1)
{
    extern __shared__ float sm[];
    float*  KFt = sm;             // [d][j]  stride 66
    float*  WK2 = sm + OFF_WK2;   // [d][c]  stride 66
    float*  VFt = sm + OFF_VF;    // [vd][j] stride 68
    float*  WV2 = sm + OFF_WV2;   // [vd][c] stride 68
    float4* W1B = (float4*)(sm + OFF_W1B);
    float2* P2  = (float2*)(sm + OFF_P2);
    float*  BUF = sm + OFF_BUF;   // per-warp: TG_A[256] TG_B[256] SC_A[256] SC_B[256]

    int s = blockIdx.x, tid = threadIdx.x;
    int w = tid >> 5, lane = tid & 31;
    int base = s * 64;

    #pragma unroll
    for (int it = 0; it < 16; it++) {          // KF,VF transpose (coalesced LDG)
        int idx = tid + it * 512;
        int r = idx >> 7, c = idx & 127;
        KFt[c * 66 + r] = g_y[(base + r) * 384 + 128 + c];
        VFt[c * 68 + r] = g_y[(base + r) * 384 + 256 + c];
    }
    #pragma unroll
    for (int it = 0; it < 16; it++) {          // WK2 re-strided copy
        int idx = tid + it * 512;
        int row = idx >> 6, c = idx & 63;
        WK2[row * 66 + c] = g_wk2[idx];
    }
    #pragma unroll
    for (int it = 0; it < 4; it++) {           // WV2 float4 re-strided copy
        int idx = tid + it * 512;
        int row = idx >> 4, cq = idx & 15;
        *(float4*)&WV2[row * 68 + cq * 4] = *(const float4*)&g_wv2[row * 64 + cq * 4];
    }
    if (tid < 64) {
        W1B[tid] = make_float4(W1[tid * 2], W1[tid * 2 + 1], b1[tid], 0.f);
        P2[tid]  = *(const float2*)&pos[(base + tid) * 2];
    }

    // Q in registers: qreg[round][pair-slot][head]
    float qreg[2][2][4];
    #pragma unroll
    for (int r2 = 0; r2 < 2; r2++)
        #pragma unroll
        for (int p = 0; p < 2; p++) {
            int i = w + r2 * 16 + p * 32;
            #pragma unroll
            for (int h = 0; h < 4; h++)
                qreg[r2][p][h] = g_y[(base + i) * 384 + h * 32 + lane];
        }
    __syncthreads();

    float* myTG_A = BUF + w * 1024;     // T then G (A)
    float* myTG_B = myTG_A + 256;
    float* mySC_A = myTG_B + 256;
    float* mySC_B = mySC_A + 256;
    int c0 = 2 * lane, c1 = c0 + 1;     // also j0, j1

    float4 wp0 = W1B[c0], wp1 = W1B[c1];
    float2 pj0 = P2[c0],  pj1 = P2[c1];

    #pragma unroll
    for (int r2 = 0; r2 < 2; r2++) {
        int iA = w + r2 * 16, iB = iA + 32;
        float2 piA = P2[iA], piB = P2[iB];
        float dxj0A = pj0.x - piA.x, dyj0A = pj0.y - piA.y;
        float dxj1A = pj1.x - piA.x, dyj1A = pj1.y - piA.y;
        float dxj0B = pj0.x - piB.x, dyj0B = pj0.y - piB.y;
        float dxj1B = pj1.x - piB.x, dyj1B = pj1.y - piB.y;

        // ---- batched d-loop: t and qk-score for BOTH queries; K/WK2 read once ----
        float tA0[4], tA1[4], tB0[4], tB1[4];
        float sA0[4], sA1[4], sB0[4], sB1[4];
        #pragma unroll
        for (int h = 0; h < 4; h++) {
            unsigned long long taccA = 0ULL, saccA = 0ULL, taccB = 0ULL, saccB = 0ULL;
            float qhA = qreg[r2][0][h], qhB = qreg[r2][1][h];
            #pragma unroll 8
            for (int d = 0; d < 32; d++) {
                int dd = h * 32 + d;
                unsigned long long kk = *(const unsigned long long*)&KFt[dd * 66 + c0];
                unsigned long long wk = *(const unsigned long long*)&WK2[dd * 66 + c0];
                unsigned long long qdA = dup2(__shfl_sync(0xffffffffu, qhA, d));
                unsigned long long qdB = dup2(__shfl_sync(0xffffffffu, qhB, d));
                ffma2(taccA, qdA, wk);
                ffma2(saccA, qdA, kk);
                ffma2(taccB, qdB, wk);
                ffma2(saccB, qdB, kk);
            }
            float2 tp = unpk2(taccA); tA0[h] = tp.x; tA1[h] = tp.y;
            float2 sp = unpk2(saccA); sA0[h] = sp.x; sA1[h] = sp.y;
            tp = unpk2(taccB); tB0[h] = tp.x; tB1[h] = tp.y;
            sp = unpk2(saccB); sB0[h] = sp.x; sB1[h] = sp.y;
        }
        // write T ([c][h] layout), pack scores into head-pairs
        *(float4*)&myTG_A[c0 * 4] = make_float4(tA0[0], tA0[1], tA0[2], tA0[3]);
        *(float4*)&myTG_A[c1 * 4] = make_float4(tA1[0], tA1[1], tA1[2], tA1[3]);
        *(float4*)&myTG_B[c0 * 4] = make_float4(tB0[0], tB0[1], tB0[2], tB0[3]);
        *(float4*)&myTG_B[c1 * 4] = make_float4(tB1[0], tB1[1], tB1[2], tB1[3]);
        unsigned long long ajA0_01 = pk2(sA0[0], sA0[1]), ajA0_23 = pk2(sA0[2], sA0[3]);
        unsigned long long ajA1_01 = pk2(sA1[0], sA1[1]), ajA1_23 = pk2(sA1[2], sA1[3]);
        unsigned long long ajB0_01 = pk2(sB0[0], sB0[1]), ajB0_23 = pk2(sB0[2], sB0[3]);
        unsigned long long ajB1_01 = pk2(sB1[0], sB1[1]), ajB1_23 = pk2(sB1[2], sB1[3]);
        __syncwarp();

        // ---- batched rel-encoding contribution (W1B read once per pair) ----
        #pragma unroll 4
        for (int c = 0; c < 64; c++) {
            float4 wb = W1B[c];
            F4U tvA; tvA.f4 = *(const float4*)&myTG_A[c * 4];
            F4U tvB; tvB.f4 = *(const float4*)&myTG_B[c * 4];
            float h0A = fmaxf(fmaf(wb.x, dxj0A, fmaf(wb.y, dyj0A, wb.z)), 0.f);
            float h1A = fmaxf(fmaf(wb.x, dxj1A, fmaf(wb.y, dyj1A, wb.z)), 0.f);
            float h0B = fmaxf(fmaf(wb.x, dxj0B, fmaf(wb.y, dyj0B, wb.z)), 0.f);
            float h1B = fmaxf(fmaf(wb.x, dxj1B, fmaf(wb.y, dyj1B, wb.z)), 0.f);
            unsigned long long h0Ad = dup2(h0A), h1Ad = dup2(h1A);
            unsigned long long h0Bd = dup2(h0B), h1Bd = dup2(h1B);
            ffma2(ajA0_01, tvA.u[0], h0Ad); ffma2(ajA0_23, tvA.u[1], h0Ad);
            ffma2(ajA1_01, tvA.u[0], h1Ad); ffma2(ajA1_23, tvA.u[1], h1Ad);
            ffma2(ajB0_01, tvB.u[0], h0Bd); ffma2(ajB0_23, tvB.u[1], h0Bd);
            ffma2(ajB1_01, tvB.u[0], h1Bd); ffma2(ajB1_23, tvB.u[1], h1Bd);
        }

        // ---- softmax per query per head ----
        {
            float a0[4], a1[4];
            float2 u;
            u = unpk2(ajA0_01); a0[0] = u.x; a0[1] = u.y;
            u = unpk2(ajA0_23); a0[2] = u.x; a0[3] = u.y;
            u = unpk2(ajA1_01); a1[0] = u.x; a1[1] = u.y;
            u = unpk2(ajA1_23); a1[2] = u.x; a1[3] = u.y;
            #pragma unroll
            for (int h = 0; h < 4; h++) {
                float m = fmaxf(a0[h], a1[h]);
                #pragma unroll
                for (int off = 16; off; off >>= 1)
                    m = fmaxf(m, __shfl_xor_sync(0xffffffffu, m, off));
                float e0 = __expf(a0[h] - m), e1 = __expf(a1[h] - m);
                float ss = e0 + e1;
                #pragma unroll
                for (int off = 16; off; off >>= 1)
                    ss += __shfl_xor_sync(0xffffffffu, ss, off);
                float rinv = 1.f / ss;
                *(float2*)&mySC_A[h * 64 + c0] = make_float2(e0 * rinv, e1 * rinv);
            }
            u = unpk2(ajB0_01); a0[0] = u.x; a0[1] = u.y;
            u = unpk2(ajB0_23); a0[2] = u.x; a0[3] = u.y;
            u = unpk2(ajB1_01); a1[0] = u.x; a1[1] = u.y;
            u = unpk2(ajB1_23); a1[2] = u.x; a1[3] = u.y;
            #pragma unroll
            for (int h = 0; h < 4; h++) {
                float m = fmaxf(a0[h], a1[h]);
                #pragma unroll
                for (int off = 16; off; off >>= 1)
                    m = fmaxf(m, __shfl_xor_sync(0xffffffffu, m, off));
                float e0 = __expf(a0[h] - m), e1 = __expf(a1[h] - m);
                float ss = e0 + e1;
                #pragma unroll
                for (int off = 16; off; off >>= 1)
                    ss += __shfl_xor_sync(0xffffffffu, ss, off);
                float rinv = 1.f / ss;
                *(float2*)&mySC_B[h * 64 + c0] = make_float2(e0 * rinv, e1 * rinv);
            }
        }
        __syncwarp();

        // ---- batched g-loop: hid rows per query; P2 read once ----
        {
            float gA0[4] = {0, 0, 0, 0}, gA1[4] = {0, 0, 0, 0};
            float gB0[4] = {0, 0, 0, 0}, gB1[4] = {0, 0, 0, 0};
            #pragma unroll 4
            for (int j = 0; j < 64; j++) {
                float2 pj = P2[j];
                float dxA = pj.x - piA.x, dyA = pj.y - piA.y;
                float dxB = pj.x - piB.x, dyB = pj.y - piB.y;
                float h0A = fmaxf(fmaf(wp0.x, dxA, fmaf(wp0.y, dyA, wp0.z)), 0.f);
                float h1A = fmaxf(fmaf(wp1.x, dxA, fmaf(wp1.y, dyA, wp1.z)), 0.f);
                float h0B = fmaxf(fmaf(wp0.x, dxB, fmaf(wp0.y, dyB, wp0.z)), 0.f);
                float h1B = fmaxf(fmaf(wp1.x, dxB, fmaf(wp1.y, dyB, wp1.z)), 0.f);
                #pragma unroll
                for (int h = 0; h < 4; h++) {
                    float aA = mySC_A[h * 64 + j];
                    float aB = mySC_B[h * 64 + j];
                    gA0[h] = fmaf(aA, h0A, gA0[h]);
                    gA1[h] = fmaf(aA, h1A, gA1[h]);
                    gB0[h] = fmaf(aB, h0B, gB0[h]);
                    gB1[h] = fmaf(aB, h1B, gB1[h]);
                }
            }
            #pragma unroll
            for (int h = 0; h < 4; h++) {
                *(float2*)&myTG_A[h * 64 + c0] = make_float2(gA0[h], gA1[h]);  // G (overwrites T)
                *(float2*)&myTG_B[h * 64 + c0] = make_float2(gB0[h], gB1[h]);
            }
        }
        __syncwarp();

        // ---- batched out-loop: VF/WV2 rows read once per pair ----
        #pragma unroll
        for (int h = 0; h < 4; h++) {
            unsigned long long pA = 0ULL, pB = 0ULL;
            const float* vr  = VFt + (h * 32 + lane) * 68;
            const float* arA = mySC_A + h * 64;
            const float* arB = mySC_B + h * 64;
            #pragma unroll
            for (int jq = 0; jq < 16; jq++) {
                F4U vv, avA, avB;
                vv.f4  = *(const float4*)&vr[jq * 4];
                avA.f4 = *(const float4*)&arA[jq * 4];
                avB.f4 = *(const float4*)&arB[jq * 4];
                ffma2(pA, avA.u[0], vv.u[0]);
                ffma2(pA, avA.u[1], vv.u[1]);
                ffma2(pB, avB.u[0], vv.u[0]);
                ffma2(pB, avB.u[1], vv.u[1]);
            }
            const float* wr  = WV2 + (h * 32 + lane) * 68;
            const float* grA = myTG_A + h * 64;
            const float* grB = myTG_B + h * 64;
            #pragma unroll
            for (int cq = 0; cq < 16; cq++) {
                F4U wv, gvA, gvB;
                wv.f4  = *(const float4*)&wr[cq * 4];
                gvA.f4 = *(const float4*)&grA[cq * 4];
                gvB.f4 = *(const float4*)&grB[cq * 4];
                ffma2(pA, gvA.u[0], wv.u[0]);
                ffma2(pA, gvA.u[1], wv.u[1]);
                ffma2(pB, gvB.u[0], wv.u[0]);
                ffma2(pB, gvB.u[1], wv.u[1]);
            }
            float2 prA = unpk2(pA), prB = unpk2(pB);
            g_ctx[(base + iA) * 128 + h * 32 + lane] = prA.x + prA.y;
            g_ctx[(base + iB) * 128 + h * 32 + lane] = prB.x + prB.y;
        }
        __syncwarp();
    }
}

// ---------------- launch ----------------
extern "C" void kernel_launch(void* const* d_in, const int* in_sizes, int n_in,
                              void* d_out, int out_size)
{
    const float* node_features = (const float*)d_in[0];
    const float* positions     = (const float*)d_in[1];
    const float* W1            = (const float*)d_in[2];
    const float* b1            = (const float*)d_in[3];
    const float* W2            = (const float*)d_in[4];
    const float* b2            = (const float*)d_in[5];
    const float* in_proj_w     = (const float*)d_in[6];
    const float* in_proj_b     = (const float*)d_in[7];
    const float* out_w         = (const float*)d_in[8];
    const float* out_b         = (const float*)d_in[9];
    const float* proj_w        = (const float*)d_in[10];
    const float* proj_b        = (const float*)d_in[11];
    float* out = (float*)d_out;

    size_t attn_smem = (size_t)ATTN_SMEM_FLOATS * sizeof(float);
    cudaFuncSetAttribute(attn_kernel, cudaFuncAttributeMaxDynamicSharedMemorySize,
                         (int)attn_smem);

    prep_kernel<<<130, 256>>>(in_proj_w, in_proj_b, W2, b2, out_w, out_b, proj_w, proj_b);
    qkv_gemm<<<dim3(TOTAL / 128, 384 / 64), 256>>>(node_features, in_proj_w);
    attn_kernel<<<S_SCENES, 512, attn_smem>>>(positions, W1, b1);
    out_gemm<<<dim3(TOTAL / 128, 128 / 64), 256>>>(node_features, proj_w, out);
}

// round 8
// speedup vs baseline: 1.3038x; 1.0637x over previous
#include <cuda_runtime.h>
#include <math.h>

#define S_SCENES 128
#define N_PED    64
#define HID      128
#define TOTAL    (S_SCENES * N_PED)   // 8192
#define QSCALE   0.17677669529663687f // 1/sqrt(32)

// ---------------- device scratch ----------------
__device__ float g_y[TOTAL * 384];    // q | kf | vf  (q pre-scaled)
__device__ float g_ctx[TOTAL * HID];  // attention context
__device__ float g_wk2[HID * 64];     // Wk @ W2   (L2-resident, staged into smem chunks)
__device__ float g_wv2[HID * 64];     // Wv @ W2   (L2-resident, staged into smem chunks)
__device__ float g_wco[HID * HID];    // P2 @ out_w
__device__ float g_bias384[384];      // [bq | bk+Wk@b2 | bv+Wv@b2]
__device__ float g_bco[HID];          // proj_b + P2 @ out_b

// ---------------- f32x2 helpers ----------------
__device__ __forceinline__ unsigned long long dup2(float x) {
    unsigned long long r;
    asm("mov.b64 %0, {%1, %1};" : "=l"(r) : "r"(__float_as_uint(x)));
    return r;
}
__device__ __forceinline__ unsigned long long pk2(float lo, float hi) {
    unsigned long long r;
    asm("mov.b64 %0, {%1, %2};" : "=l"(r) : "r"(__float_as_uint(lo)), "r"(__float_as_uint(hi)));
    return r;
}
__device__ __forceinline__ void ffma2(unsigned long long& d,
                                      unsigned long long a, unsigned long long b) {
    asm("fma.rn.f32x2 %0, %1, %2, %0;" : "+l"(d) : "l"(a), "l"(b));
}
__device__ __forceinline__ float2 unpk2(unsigned long long v) {
    unsigned lo, hi;
    asm("mov.b64 {%0, %1}, %2;" : "=r"(lo), "=r"(hi) : "l"(v));
    return make_float2(__uint_as_float(lo), __uint_as_float(hi));
}
union F4U { float4 f4; unsigned long long u[2]; float f[4]; };

// ---------------- K1: combine weights ----------------
__global__ void prep_kernel(const float* __restrict__ ipw,
                            const float* __restrict__ ipb,
                            const float* __restrict__ W2,
                            const float* __restrict__ b2,
                            const float* __restrict__ outw,
                            const float* __restrict__ outb,
                            const float* __restrict__ pw,
                            const float* __restrict__ pb)
{
    int idx = blockIdx.x * blockDim.x + threadIdx.x;
    if (idx < 384) {
        float v = ipb[idx];
        if (idx >= 128) {
            const float* wrow = ipw + idx * 128;
            float acc = 0.f;
            #pragma unroll 8
            for (int d = 0; d < 128; d++) acc += wrow[d] * b2[d];
            v += acc;
        }
        g_bias384[idx] = v;
        return;
    }
    int t = idx - 384;
    if (t < 8192) {
        int hd = t >> 6, c = t & 63;
        const float* wrow = ipw + (128 + hd) * 128;
        float acc = 0.f;
        #pragma unroll 8
        for (int d = 0; d < 128; d++) acc += wrow[d] * W2[d * 64 + c];
        g_wk2[t] = acc;
        return;
    }
    t -= 8192;
    if (t < 8192) {
        int hd = t >> 6, c = t & 63;
        const float* wrow = ipw + (256 + hd) * 128;
        float acc = 0.f;
        #pragma unroll 8
        for (int d = 0; d < 128; d++) acc += wrow[d] * W2[d * 64 + c];
        g_wv2[t] = acc;
        return;
    }
    t -= 8192;
    if (t < 16384) {
        int n = t >> 7, k = t & 127;
        const float* p2 = pw + n * 256 + 128;
        float acc = 0.f;
        #pragma unroll 8
        for (int d = 0; d < 128; d++) acc += p2[d] * outw[d * 128 + k];
        g_wco[t] = acc;
        return;
    }
    t -= 16384;
    if (t < 128) {
        const float* p2 = pw + t * 256 + 128;
        float acc = pb[t];
        #pragma unroll 8
        for (int d = 0; d < 128; d++) acc += p2[d] * outb[d];
        g_bco[t] = acc;
    }
}

// ---------------- GEMMs: proven config (128x64 tile, BK=32, 256 thr, 8x4 micro) ----------------
#define AS_P 132
#define BS_P 68

__global__ void __launch_bounds__(256) qkv_gemm(const float* __restrict__ X,
                                                const float* __restrict__ W)
{
    __shared__ float As[32][AS_P];
    __shared__ float Bs[32][BS_P];
    int m0 = blockIdx.x * 128, n0 = blockIdx.y * 64;
    int tid = threadIdx.x, tx = tid & 15, ty = tid >> 4;

    unsigned long long acc[4][4];
    #pragma unroll
    for (int r = 0; r < 4; r++)
        #pragma unroll
        for (int c = 0; c < 4; c++) acc[r][c] = 0ULL;

    float4 pa[4], pb[2];
    int rowA[4], kqA[4], rowB[2], kqB[2];
    #pragma unroll
    for (int i = 0; i < 4; i++) { int idx = tid + i * 256; rowA[i] = idx >> 3; kqA[i] = idx & 7; }
    #pragma unroll
    for (int i = 0; i < 2; i++) { int idx = tid + i * 256; rowB[i] = idx >> 3; kqB[i] = idx & 7; }

    #pragma unroll
    for (int i = 0; i < 4; i++) pa[i] = *(const float4*)&X[(m0 + rowA[i]) * 128 + kqA[i] * 4];
    #pragma unroll
    for (int i = 0; i < 2; i++) pb[i] = *(const float4*)&W[(n0 + rowB[i]) * 128 + kqB[i] * 4];

    for (int kc = 0; kc < 4; kc++) {
        #pragma unroll
        for (int i = 0; i < 4; i++) {
            As[kqA[i] * 4 + 0][rowA[i]] = pa[i].x;
            As[kqA[i] * 4 + 1][rowA[i]] = pa[i].y;
            As[kqA[i] * 4 + 2][rowA[i]] = pa[i].z;
            As[kqA[i] * 4 + 3][rowA[i]] = pa[i].w;
        }
        #pragma unroll
        for (int i = 0; i < 2; i++) {
            Bs[kqB[i] * 4 + 0][rowB[i]] = pb[i].x;
            Bs[kqB[i] * 4 + 1][rowB[i]] = pb[i].y;
            Bs[kqB[i] * 4 + 2][rowB[i]] = pb[i].z;
            Bs[kqB[i] * 4 + 3][rowB[i]] = pb[i].w;
        }
        __syncthreads();
        if (kc < 3) {
            int k0 = (kc + 1) * 32;
            #pragma unroll
            for (int i = 0; i < 4; i++) pa[i] = *(const float4*)&X[(m0 + rowA[i]) * 128 + k0 + kqA[i] * 4];
            #pragma unroll
            for (int i = 0; i < 2; i++) pb[i] = *(const float4*)&W[(n0 + rowB[i]) * 128 + k0 + kqB[i] * 4];
        }
        #pragma unroll
        for (int k = 0; k < 32; k++) {
            F4U a0, a1, b;
            a0.f4 = *(const float4*)&As[k][ty * 8];
            a1.f4 = *(const float4*)&As[k][ty * 8 + 4];
            b.f4  = *(const float4*)&Bs[k][tx * 4];
            unsigned long long bd[4];
            #pragma unroll
            for (int c = 0; c < 4; c++) bd[c] = dup2(b.f[c]);
            #pragma unroll
            for (int c = 0; c < 4; c++) {
                ffma2(acc[0][c], a0.u[0], bd[c]);
                ffma2(acc[1][c], a0.u[1], bd[c]);
                ffma2(acc[2][c], a1.u[0], bd[c]);
                ffma2(acc[3][c], a1.u[1], bd[c]);
            }
        }
        __syncthreads();
    }
    float scale = (n0 < 128) ? QSCALE : 1.0f;
    int n = n0 + tx * 4;
    float4 b4 = *(const float4*)&g_bias384[n];
    #pragma unroll
    for (int r2 = 0; r2 < 4; r2++) {
        float2 p0 = unpk2(acc[r2][0]), p1 = unpk2(acc[r2][1]);
        float2 p2 = unpk2(acc[r2][2]), p3 = unpk2(acc[r2][3]);
        int m = m0 + ty * 8 + r2 * 2;
        float4 lo = make_float4((p0.x + b4.x) * scale, (p1.x + b4.y) * scale,
                                (p2.x + b4.z) * scale, (p3.x + b4.w) * scale);
        float4 hi = make_float4((p0.y + b4.x) * scale, (p1.y + b4.y) * scale,
                                (p2.y + b4.z) * scale, (p3.y + b4.w) * scale);
        *(float4*)&g_y[m * 384 + n] = lo;
        *(float4*)&g_y[(m + 1) * 384 + n] = hi;
    }
}

__global__ void __launch_bounds__(256) out_gemm(const float* __restrict__ X,
                                                const float* __restrict__ PW,
                                                float* __restrict__ OUT)
{
    __shared__ float As[32][AS_P];
    __shared__ float Bs[32][BS_P];
    int m0 = blockIdx.x * 128, n0 = blockIdx.y * 64;
    int tid = threadIdx.x, tx = tid & 15, ty = tid >> 4;

    unsigned long long acc[4][4];
    #pragma unroll
    for (int r = 0; r < 4; r++)
        #pragma unroll
        for (int c = 0; c < 4; c++) acc[r][c] = 0ULL;

    float4 pa[4], pb[2];
    int rowA[4], kqA[4], rowB[2], kqB[2];
    #pragma unroll
    for (int i = 0; i < 4; i++) { int idx = tid + i * 256; rowA[i] = idx >> 3; kqA[i] = idx & 7; }
    #pragma unroll
    for (int i = 0; i < 2; i++) { int idx = tid + i * 256; rowB[i] = idx >> 3; kqB[i] = idx & 7; }

    #pragma unroll
    for (int i = 0; i < 4; i++) pa[i] = *(const float4*)&X[(m0 + rowA[i]) * 128 + kqA[i] * 4];
    #pragma unroll
    for (int i = 0; i < 2; i++) pb[i] = *(const float4*)&PW[(n0 + rowB[i]) * 256 + kqB[i] * 4];

    for (int kc = 0; kc < 8; kc++) {
        #pragma unroll
        for (int i = 0; i < 4; i++) {
            As[kqA[i] * 4 + 0][rowA[i]] = pa[i].x;
            As[kqA[i] * 4 + 1][rowA[i]] = pa[i].y;
            As[kqA[i] * 4 + 2][rowA[i]] = pa[i].z;
            As[kqA[i] * 4 + 3][rowA[i]] = pa[i].w;
        }
        #pragma unroll
        for (int i = 0; i < 2; i++) {
            Bs[kqB[i] * 4 + 0][rowB[i]] = pb[i].x;
            Bs[kqB[i] * 4 + 1][rowB[i]] = pb[i].y;
            Bs[kqB[i] * 4 + 2][rowB[i]] = pb[i].z;
            Bs[kqB[i] * 4 + 3][rowB[i]] = pb[i].w;
        }
        __syncthreads();
        if (kc < 7) {
            int knext = kc + 1;
            int kcol = (knext & 3) * 32;
            if (knext < 4) {
                #pragma unroll
                for (int i = 0; i < 4; i++) pa[i] = *(const float4*)&X[(m0 + rowA[i]) * 128 + kcol + kqA[i] * 4];
                #pragma unroll
                for (int i = 0; i < 2; i++) pb[i] = *(const float4*)&PW[(n0 + rowB[i]) * 256 + kcol + kqB[i] * 4];
            } else {
                #pragma unroll
                for (int i = 0; i < 4; i++) pa[i] = *(const float4*)&g_ctx[(m0 + rowA[i]) * 128 + kcol + kqA[i] * 4];
                #pragma unroll
                for (int i = 0; i < 2; i++) pb[i] = *(const float4*)&g_wco[(n0 + rowB[i]) * 128 + kcol + kqB[i] * 4];
            }
        }
        #pragma unroll
        for (int k = 0; k < 32; k++) {
            F4U a0, a1, b;
            a0.f4 = *(const float4*)&As[k][ty * 8];
            a1.f4 = *(const float4*)&As[k][ty * 8 + 4];
            b.f4  = *(const float4*)&Bs[k][tx * 4];
            unsigned long long bd[4];
            #pragma unroll
            for (int c = 0; c < 4; c++) bd[c] = dup2(b.f[c]);
            #pragma unroll
            for (int c = 0; c < 4; c++) {
                ffma2(acc[0][c], a0.u[0], bd[c]);
                ffma2(acc[1][c], a0.u[1], bd[c]);
                ffma2(acc[2][c], a1.u[0], bd[c]);
                ffma2(acc[3][c], a1.u[1], bd[c]);
            }
        }
        __syncthreads();
    }
    int n = n0 + tx * 4;
    float4 b4 = *(const float4*)&g_bco[n];
    #pragma unroll
    for (int r2 = 0; r2 < 4; r2++) {
        float2 p0 = unpk2(acc[r2][0]), p1 = unpk2(acc[r2][1]);
        float2 p2 = unpk2(acc[r2][2]), p3 = unpk2(acc[r2][3]);
        int m = m0 + ty * 8 + r2 * 2;
        float4 lo = make_float4(p0.x + b4.x, p1.x + b4.y, p2.x + b4.z, p3.x + b4.w);
        float4 hi = make_float4(p0.y + b4.x, p1.y + b4.y, p2.y + b4.z, p3.y + b4.w);
        *(float4*)&OUT[m * 128 + n] = lo;
        *(float4*)&OUT[(m + 1) * 128 + n] = hi;
    }
}

// ---------------- K3: attention, 512 threads, 16 warps x 4 queries, 1 round ----------------
// smem floats:
//   KFt[128][66]=8448 (u64 reads: even stride) | VFt[128][65]=8320 (scalar) |
//   UG[64][66]=4224 (u64 reads) | W1B f4[64]=256 | P2 f2[64]=128 |
//   WST[2176]: K-stage [32][68] f4-aligned / V-stage transposed [64][33] |
//   BUF 16*2048=32768  => 56320 floats (220 KB)
#define STK 66
#define STV 65
#define STU 66
#define STS 68
#define OFF_VF   8448
#define OFF_UG   16768
#define OFF_W1B  20992
#define OFF_P2   21248
#define OFF_WST  21376
#define OFF_BUF  23552
#define ATTN_SMEM_FLOATS (23552 + 16 * 2048)

__global__ void __launch_bounds__(512) attn_kernel(const float* __restrict__ pos,
                                                   const float* __restrict__ W1,
                                                   const float* __restrict__ b1)
{
    extern __shared__ float sm[];
    float*  KFt = sm;                       // [d][j] stride 66
    float*  VFt = sm + OFF_VF;              // [vd][j] stride 65
    float*  UG  = sm + OFF_UG;              // [j][c] stride 66 : W1·pos_j
    float4* W1B = (float4*)(sm + OFF_W1B);  // (w1x, w1y, b1, 0)
    float2* P2  = (float2*)(sm + OFF_P2);
    float*  WST = sm + OFF_WST;             // staging chunk
    float*  BUF = sm + OFF_BUF;             // per-warp: TG4[1024] SC4[1024]

    int s = blockIdx.x, tid = threadIdx.x;
    int w = tid >> 5, lane = tid & 31;
    int base = s * 64;

    // ---- init loads ----
    #pragma unroll
    for (int it = 0; it < 16; it++) {       // KF,VF transpose (coalesced LDG)
        int idx = tid + it * 512;
        int r = idx >> 7, c = idx & 127;
        KFt[c * STK + r] = g_y[(base + r) * 384 + 128 + c];
        VFt[c * STV + r] = g_y[(base + r) * 384 + 256 + c];
    }
    if (tid < 64) {
        W1B[tid] = make_float4(W1[tid * 2], W1[tid * 2 + 1], b1[tid], 0.f);
        P2[tid]  = *(const float2*)&pos[(base + tid) * 2];
    }
    __syncthreads();
    // UG[j][c] = w1x[c]*px[j] + w1y[c]*py[j]
    #pragma unroll
    for (int it = 0; it < 8; it++) {
        int idx = tid + it * 512;
        int j = idx >> 6, c = idx & 63;
        float4 wb = W1B[c];
        float2 pj = P2[j];
        UG[j * STU + c] = fmaf(wb.x, pj.x, wb.y * pj.y);
    }
    // q in registers
    float qreg[4][4];
    #pragma unroll
    for (int q = 0; q < 4; q++) {
        int i = w + q * 16;
        #pragma unroll
        for (int h = 0; h < 4; h++)
            qreg[q][h] = g_y[(base + i) * 384 + h * 32 + lane];
    }
    int c0 = 2 * lane, c1 = c0 + 1;
    float2 pj0 = P2[c0], pj1 = P2[c1];
    float dx0[4], dy0[4], dx1[4], dy1[4];
    #pragma unroll
    for (int q = 0; q < 4; q++) {
        float2 pi = P2[w + q * 16];
        dx0[q] = pj0.x - pi.x; dy0[q] = pj0.y - pi.y;
        dx1[q] = pj1.x - pi.x; dy1[q] = pj1.y - pi.y;
    }

    float* myT  = BUF + w * 2048;   // T4 [q][c][4] then G4 [h][c][4]
    float* mySC = myT + 1024;       // SC4 [h][j][4]

    // ---- score + T pass (WK2 staged per head, [32][68] float4-aligned) ----
    unsigned long long spk[4][4];   // [q][h] packed (s_j0, s_j1)
    unsigned long long tpk[4][4];
    int srow = tid >> 4, scq = tid & 15;
    for (int h = 0; h < 4; h++) {
        __syncthreads();
        *(float4*)&WST[srow * STS + scq * 4] =
            *(const float4*)&g_wk2[(h * 32 + srow) * 64 + scq * 4];
        __syncthreads();
        unsigned long long tacc[4] = {0ULL, 0ULL, 0ULL, 0ULL};
        unsigned long long sacc[4] = {0ULL, 0ULL, 0ULL, 0ULL};
        #pragma unroll 8
        for (int d = 0; d < 32; d++) {
            int dd = h * 32 + d;
            unsigned long long kk = *(const unsigned long long*)&KFt[dd * STK + c0];
            unsigned long long wk = *(const unsigned long long*)&WST[d * STS + c0];
            #pragma unroll
            for (int q = 0; q < 4; q++) {
                unsigned long long qd = dup2(__shfl_sync(0xffffffffu, qreg[q][h], d));
                ffma2(tacc[q], qd, wk);
                ffma2(sacc[q], qd, kk);
            }
        }
        #pragma unroll
        for (int q = 0; q < 4; q++) { tpk[q][h] = tacc[q]; spk[q][h] = sacc[q]; }
    }
    // dump T to smem: T4 [q][c][4] = (t_h0..t_h3)
    #pragma unroll
    for (int q = 0; q < 4; q++) {
        float2 t0 = unpk2(tpk[q][0]), t1 = unpk2(tpk[q][1]);
        float2 t2 = unpk2(tpk[q][2]), t3 = unpk2(tpk[q][3]);
        *(float4*)&myT[q * 256 + c0 * 4] = make_float4(t0.x, t1.x, t2.x, t3.x);
        *(float4*)&myT[q * 256 + c1 * 4] = make_float4(t0.y, t1.y, t2.y, t3.y);
    }
    // repack scores into head-pair accumulators
    unsigned long long aj0_01[4], aj0_23[4], aj1_01[4], aj1_23[4];
    #pragma unroll
    for (int q = 0; q < 4; q++) {
        float2 s0 = unpk2(spk[q][0]), s1 = unpk2(spk[q][1]);
        float2 s2 = unpk2(spk[q][2]), s3 = unpk2(spk[q][3]);
        aj0_01[q] = pk2(s0.x, s1.x); aj0_23[q] = pk2(s2.x, s3.x);
        aj1_01[q] = pk2(s0.y, s1.y); aj1_23[q] = pk2(s2.y, s3.y);
    }
    __syncwarp();

    // ---- rel-encoding contribution ----
    #pragma unroll 4
    for (int c = 0; c < 64; c++) {
        float4 wb = W1B[c];
        #pragma unroll
        for (int q = 0; q < 4; q++) {
            F4U tv; tv.f4 = *(const float4*)&myT[q * 256 + c * 4];
            float h0 = fmaxf(fmaf(wb.x, dx0[q], fmaf(wb.y, dy0[q], wb.z)), 0.f);
            float h1 = fmaxf(fmaf(wb.x, dx1[q], fmaf(wb.y, dy1[q], wb.z)), 0.f);
            unsigned long long h0d = dup2(h0), h1d = dup2(h1);
            ffma2(aj0_01[q], tv.u[0], h0d);
            ffma2(aj0_23[q], tv.u[1], h0d);
            ffma2(aj1_01[q], tv.u[0], h1d);
            ffma2(aj1_23[q], tv.u[1], h1d);
        }
    }
    __syncwarp();   // all lanes done reading T before G overwrites

    // ---- softmax (all 4 queries) ----
    float e0[4][4], e1[4][4];   // [q][h]
    #pragma unroll
    for (int q = 0; q < 4; q++) {
        float a0[4], a1[4];
        float2 u;
        u = unpk2(aj0_01[q]); a0[0] = u.x; a0[1] = u.y;
        u = unpk2(aj0_23[q]); a0[2] = u.x; a0[3] = u.y;
        u = unpk2(aj1_01[q]); a1[0] = u.x; a1[1] = u.y;
        u = unpk2(aj1_23[q]); a1[2] = u.x; a1[3] = u.y;
        #pragma unroll
        for (int h = 0; h < 4; h++) {
            float m = fmaxf(a0[h], a1[h]);
            #pragma unroll
            for (int off = 16; off; off >>= 1)
                m = fmaxf(m, __shfl_xor_sync(0xffffffffu, m, off));
            float ex0 = __expf(a0[h] - m), ex1 = __expf(a1[h] - m);
            float ss = ex0 + ex1;
            #pragma unroll
            for (int off = 16; off; off >>= 1)
                ss += __shfl_xor_sync(0xffffffffu, ss, off);
            float rinv = 1.f / ss;
            e0[q][h] = ex0 * rinv;
            e1[q][h] = ex1 * rinv;
        }
    }
    // write SC4 [h][j][4]
    #pragma unroll
    for (int h = 0; h < 4; h++) {
        *(float4*)&mySC[(h * 64 + c0) * 4] = make_float4(e0[0][h], e0[1][h], e0[2][h], e0[3][h]);
        *(float4*)&mySC[(h * 64 + c1) * 4] = make_float4(e1[0][h], e1[1][h], e1[2][h], e1[3][h]);
    }
    __syncwarp();

    // ---- g-loop: g[q][h][c] = sum_j attn * relu(UG[j][c] - vi[q][c]) ----
    float vi0[4], vi1[4];
    {
        float b1c0 = W1B[c0].z, b1c1 = W1B[c1].z;
        #pragma unroll
        for (int q = 0; q < 4; q++) {
            int i = w + q * 16;
            vi0[q] = UG[i * STU + c0] - b1c0;
            vi1[q] = UG[i * STU + c1] - b1c1;
        }
    }
    float g0[4][4], g1[4][4];   // [q][h]
    #pragma unroll
    for (int q = 0; q < 4; q++)
        #pragma unroll
        for (int h = 0; h < 4; h++) { g0[q][h] = 0.f; g1[q][h] = 0.f; }
    #pragma unroll 2
    for (int j = 0; j < 64; j++) {
        float2 ug = unpk2(*(const unsigned long long*)&UG[j * STU + c0]);
        float h0q[4], h1q[4];
        #pragma unroll
        for (int q = 0; q < 4; q++) {
            h0q[q] = fmaxf(ug.x - vi0[q], 0.f);
            h1q[q] = fmaxf(ug.y - vi1[q], 0.f);
        }
        #pragma unroll
        for (int h = 0; h < 4; h++) {
            F4U a4; a4.f4 = *(const float4*)&mySC[(h * 64 + j) * 4];
            #pragma unroll
            for (int q = 0; q < 4; q++) {
                g0[q][h] = fmaf(a4.f[q], h0q[q], g0[q][h]);
                g1[q][h] = fmaf(a4.f[q], h1q[q], g1[q][h]);
            }
        }
    }
    // write G4 [h][c][4] (overwrites T)
    #pragma unroll
    for (int h = 0; h < 4; h++) {
        *(float4*)&myT[(h * 64 + c0) * 4] = make_float4(g0[0][h], g0[1][h], g0[2][h], g0[3][h]);
        *(float4*)&myT[(h * 64 + c1) * 4] = make_float4(g1[0][h], g1[1][h], g1[2][h], g1[3][h]);
    }
    __syncwarp();

    // ---- out: ctx = attn@VF + g@WV2^T  (WV2 staged TRANSPOSED [c][vd_local] stride 33) ----
    for (int h = 0; h < 4; h++) {
        __syncthreads();
        #pragma unroll
        for (int it = 0; it < 4; it++) {    // 2048 elems / 512 threads
            int idx = tid + it * 512;
            int row = idx >> 6, c = idx & 63;   // row = vd_local, coalesced gmem read
            WST[c * 33 + row] = g_wv2[(h * 32 + row) * 64 + c];
        }
        __syncthreads();
        float cacc[4] = {0.f, 0.f, 0.f, 0.f};
        int vd = h * 32 + lane;
        const float* vr = VFt + vd * STV;
        #pragma unroll 4
        for (int j = 0; j < 64; j++) {
            float vv = vr[j];
            F4U a4; a4.f4 = *(const float4*)&mySC[(h * 64 + j) * 4];
            #pragma unroll
            for (int q = 0; q < 4; q++) cacc[q] = fmaf(a4.f[q], vv, cacc[q]);
        }
        #pragma unroll 4
        for (int c = 0; c < 64; c++) {
            float wv = WST[c * 33 + lane];      // stride-1 across lanes: conflict-free
            F4U g4; g4.f4 = *(const float4*)&myT[(h * 64 + c) * 4];
            #pragma unroll
            for (int q = 0; q < 4; q++) cacc[q] = fmaf(g4.f[q], wv, cacc[q]);
        }
        #pragma unroll
        for (int q = 0; q < 4; q++)
            g_ctx[(base + w + q * 16) * 128 + vd] = cacc[q];
    }
}

// ---------------- launch ----------------
extern "C" void kernel_launch(void* const* d_in, const int* in_sizes, int n_in,
                              void* d_out, int out_size)
{
    const float* node_features = (const float*)d_in[0];
    const float* positions     = (const float*)d_in[1];
    const float* W1            = (const float*)d_in[2];
    const float* b1            = (const float*)d_in[3];
    const float* W2            = (const float*)d_in[4];
    const float* b2            = (const float*)d_in[5];
    const float* in_proj_w     = (const float*)d_in[6];
    const float* in_proj_b     = (const float*)d_in[7];
    const float* out_w         = (const float*)d_in[8];
    const float* out_b         = (const float*)d_in[9];
    const float* proj_w        = (const float*)d_in[10];
    const float* proj_b        = (const float*)d_in[11];
    float* out = (float*)d_out;

    size_t attn_smem = (size_t)ATTN_SMEM_FLOATS * sizeof(float);
    cudaFuncSetAttribute(attn_kernel, cudaFuncAttributeMaxDynamicSharedMemorySize,
                         (int)attn_smem);

    prep_kernel<<<130, 256>>>(in_proj_w, in_proj_b, W2, b2, out_w, out_b, proj_w, proj_b);
    qkv_gemm<<<dim3(TOTAL / 128, 384 / 64), 256>>>(node_features, in_proj_w);
    attn_kernel<<<S_SCENES, 512, attn_smem>>>(positions, W1, b1);
    out_gemm<<<dim3(TOTAL / 128, 128 / 64), 256>>>(node_features, proj_w, out);
}